// round 1
// baseline (speedup 1.0000x reference)
#include <cuda_runtime.h>
#include <math.h>

#define Dd  512
#define Hh  8
#define HD  64
#define Bb  2
#define Ss  256
#define Ff  2048
#define Cc  4
#define Vv  32000
#define TOK (Bb*Ss)   // 512

// ---------------- device state (no allocation allowed) ----------------
__device__ float g_x [TOK*Dd];
__device__ float g_xn[TOK*Dd];
__device__ float g_q [TOK*Dd];
__device__ float g_k [TOK*Dd];
__device__ float g_v [TOK*Dd];
__device__ float g_o [TOK*Dd];
__device__ float g_ff[TOK*Ff];
__device__ int   g_cur[Bb];
__device__ float g_accp[Cc+1];
__device__ float g_acclb;

// ---------------- init ----------------
__global__ void init_k(const int* __restrict__ start) {
    if (threadIdx.x == 0) {
        g_cur[0] = start[0];
        g_cur[1] = start[1];
        #pragma unroll
        for (int i = 0; i < Cc+1; i++) g_accp[i] = 0.f;
        g_acclb = 0.f;
    }
}

// ---------------- embedding ----------------
__global__ void embed_k(const int* __restrict__ ids, const float* __restrict__ emb,
                        float* __restrict__ x) {
    int t = blockIdx.x;           // token 0..511
    int d = threadIdx.x;          // 0..511
    float scale = sqrtf((float)Dd);
    x[t*Dd + d] = emb[(size_t)ids[t]*Dd + d] * scale;
}

// ---------------- rmsnorm (block per token) ----------------
__global__ void rmsnorm_k(const float* __restrict__ x, const float* __restrict__ w,
                          const int* __restrict__ cur, float* __restrict__ out) {
    int t = blockIdx.x;
    int d = threadIdx.x;          // 512
    __shared__ float red[512];
    float v = x[t*Dd + d];
    red[d] = v*v;
    __syncthreads();
    for (int s = 256; s > 0; s >>= 1) {
        if (d < s) red[d] += red[d+s];
        __syncthreads();
    }
    float scale = rsqrtf(red[0] * (1.0f/Dd) + 1e-6f);
    const float* ww = w;
    if (cur) ww += (size_t)cur[t / Ss] * Dd;
    out[t*Dd + d] = v * scale * ww[d];
}

// ---------------- generic tiled GEMM: Out[M,N] = A[M,K] @ W[K,N] ----------------
// epi: 0 = store, 1 = res + acc, 2 = silu(acc)
// cur != null -> W += cur[batch]*K*N, batch = row_tile/Ss
__global__ void __launch_bounds__(256) gemm64(
    const float* __restrict__ A, const float* __restrict__ Wb,
    const float* __restrict__ res, float* __restrict__ Out,
    const int* __restrict__ cur, int K, int N, int epi)
{
    const int BM = 64, BN = 64, BK = 16;
    __shared__ float As[BM][BK];
    __shared__ float Bs[BK][BN];
    int tid = threadIdx.x;                 // 256 threads
    int m0 = blockIdx.y * BM, n0 = blockIdx.x * BN;
    const float* W = Wb;
    if (cur) W += (size_t)cur[m0 / Ss] * K * N;

    int ar = tid >> 2,  ac = (tid & 3)  * 4;   // A tile: 64 x 16
    int br = tid >> 4,  bc = (tid & 15) * 4;   // B tile: 16 x 64
    int ty = tid >> 4,  tx = tid & 15;

    float acc[4][4] = {};
    for (int k0 = 0; k0 < K; k0 += BK) {
        *(float4*)&As[ar][ac] = *(const float4*)&A[(size_t)(m0+ar)*K + k0 + ac];
        *(float4*)&Bs[br][bc] = *(const float4*)&W[(size_t)(k0+br)*N + n0 + bc];
        __syncthreads();
        #pragma unroll
        for (int kk = 0; kk < BK; kk++) {
            float a[4], bv[4];
            #pragma unroll
            for (int i = 0; i < 4; i++) a[i]  = As[ty*4+i][kk];
            #pragma unroll
            for (int j = 0; j < 4; j++) bv[j] = Bs[kk][tx*4+j];
            #pragma unroll
            for (int i = 0; i < 4; i++)
                #pragma unroll
                for (int j = 0; j < 4; j++) acc[i][j] += a[i]*bv[j];
        }
        __syncthreads();
    }
    #pragma unroll
    for (int i = 0; i < 4; i++) {
        int m = m0 + ty*4 + i;
        #pragma unroll
        for (int j = 0; j < 4; j++) {
            int n = n0 + tx*4 + j;
            float vout = acc[i][j];
            if (epi == 1)      vout += res[(size_t)m*N + n];
            else if (epi == 2) vout = vout / (1.f + expf(-vout));
            Out[(size_t)m*N + n] = vout;
        }
    }
}

// ---------------- rope on q,k ----------------
__global__ void rope_k(float* __restrict__ q, float* __restrict__ k) {
    int t = blockIdx.x;               // token
    int s = t % Ss;                   // position
    int i = threadIdx.x;              // 0..255 pair index in D
    int h = i >> 5;                   // head (32 pairs/head)
    int j = i & 31;
    float inv = powf(10000.f, -(2.f*j) / 64.f);
    float ang = (float)s * inv;
    float c = cosf(ang), sn = sinf(ang);
    int base = t*Dd + h*HD + 2*j;
    float q1 = q[base], q2 = q[base+1];
    q[base]   = q1*c - q2*sn;
    q[base+1] = q1*sn + q2*c;
    float k1 = k[base], k2 = k[base+1];
    k[base]   = k1*c - k2*sn;
    k[base+1] = k1*sn + k2*c;
}

// ---------------- causal attention: block per (b,h,q-row) ----------------
__global__ void attn_k(const float* __restrict__ q, const float* __restrict__ k,
                       const float* __restrict__ v, float* __restrict__ o) {
    int qi = blockIdx.x, h = blockIdx.y, b = blockIdx.z;
    int tid = threadIdx.x;            // 256
    __shared__ float qv[HD];
    __shared__ float p[Ss];
    __shared__ float red[Ss];
    int base_bh = b*Ss*Dd + h*HD;
    if (tid < HD) qv[tid] = q[base_bh + qi*Dd + tid];
    __syncthreads();

    float s;
    if (tid <= qi) {
        const float* kp = &k[base_bh + tid*Dd];
        s = 0.f;
        #pragma unroll
        for (int d2 = 0; d2 < HD; d2++) s += qv[d2] * kp[d2];
        s *= 0.125f;                 // 1/sqrt(64)
    } else {
        s = -1e30f;
    }
    red[tid] = s; __syncthreads();
    for (int st = 128; st > 0; st >>= 1) {
        if (tid < st) red[tid] = fmaxf(red[tid], red[tid+st]);
        __syncthreads();
    }
    float mx = red[0];
    __syncthreads();
    float e = expf(s - mx);
    p[tid] = e;
    red[tid] = e; __syncthreads();
    for (int st = 128; st > 0; st >>= 1) {
        if (tid < st) red[tid] += red[tid+st];
        __syncthreads();
    }
    float inv = 1.f / red[0];
    __syncthreads();
    if (tid < HD) {
        float acc = 0.f;
        for (int t2 = 0; t2 <= qi; t2++)
            acc += p[t2] * v[base_bh + t2*Dd + tid];
        o[base_bh + qi*Dd + tid] = acc * inv;
    }
}

// ---------------- gating + routing (single block) ----------------
__global__ void gate_k(const float* __restrict__ x, const float* __restrict__ gw) {
    __shared__ float pooled[Bb][Dd];
    __shared__ float red[512];
    __shared__ float sc[2*(Cc+1)];
    int tid = threadIdx.x;            // 512
    for (int b = 0; b < Bb; b++) {
        float s = 0.f;
        for (int ss = 0; ss < Ss; ss++) s += x[(size_t)(b*Ss+ss)*Dd + tid];
        pooled[b][tid] = s * (1.f/Ss);
    }
    __syncthreads();
    for (int idx = 0; idx < 2*(Cc+1); idx++) {
        int b = idx / (Cc+1), c = idx % (Cc+1);
        red[tid] = pooled[b][tid] * gw[tid*(Cc+1) + c];
        __syncthreads();
        for (int s = 256; s > 0; s >>= 1) {
            if (tid < s) red[tid] += red[tid+s];
            __syncthreads();
        }
        if (tid == 0) sc[idx] = red[0];
        __syncthreads();
    }
    if (tid == 0) {
        float p[Bb][Cc+1];
        for (int b = 0; b < Bb; b++) {
            float mx = -1e30f;
            for (int c = 0; c < Cc+1; c++) mx = fmaxf(mx, sc[b*(Cc+1)+c]);
            float sum = 0.f;
            for (int c = 0; c < Cc+1; c++) { p[b][c] = expf(sc[b*(Cc+1)+c] - mx); sum += p[b][c]; }
            for (int c = 0; c < Cc+1; c++) p[b][c] /= sum;
        }
        float lb = 0.f;
        for (int c = 0; c < Cc+1; c++) {
            g_accp[c] += p[0][c] + p[1][c];
            float avg = 0.5f * (p[0][c] + p[1][c]);
            lb += avg*avg;
        }
        g_acclb += (float)(Cc+1) * lb;
        for (int b = 0; b < Bb; b++) {
            int co = g_cur[b];
            int j1 = (co+1) & 3, j2 = (co+2) & 3;
            float s1 = sc[b*(Cc+1)+j1], s2 = sc[b*(Cc+1)+j2];
            int w;
            if (s1 > s2) w = j1;
            else if (s2 > s1) w = j2;
            else w = (j1 < j2) ? j1 : j2;   // argmax tie -> lower index
            g_cur[b] = w;
        }
    }
}

// ---------------- finalize aux losses ----------------
__global__ void fin_k(float* __restrict__ out, int n) {
    if (threadIdx.x == 0) {
        float avg[Cc+1];
        float m = 0.f;
        for (int i = 0; i < Cc+1; i++) { avg[i] = g_accp[i] * 0.25f; m += avg[i]; }
        m *= 1.f/(Cc+1);
        float var = 0.f;
        for (int i = 0; i < Cc+1; i++) { float d = avg[i] - m; var += d*d; }
        var *= 1.f/(Cc+1);
        out[n-2] = var;
        out[n-1] = g_acclb * 0.5f;
    }
}

// ---------------- host orchestration ----------------
extern "C" void kernel_launch(void* const* d_in, const int* in_sizes, int n_in,
                              void* d_out, int out_size) {
    const int*   ids   = (const int*)  d_in[0];
    const int*   start = (const int*)  d_in[1];
    const float* emb   = (const float*)d_in[2];
    const float* Wq    = (const float*)d_in[3];
    const float* Wk    = (const float*)d_in[4];
    const float* Wv    = (const float*)d_in[5];
    const float* Wo    = (const float*)d_in[6];
    const float* W1    = (const float*)d_in[7];
    const float* W2    = (const float*)d_in[8];
    const float* n1    = (const float*)d_in[9];
    const float* n2    = (const float*)d_in[10];
    const float* gw    = (const float*)d_in[11];
    const float* fnw   = (const float*)d_in[12];
    const float* fcw   = (const float*)d_in[13];
    float* out = (float*)d_out;

    float *x, *xn, *q, *k, *v, *o, *ff;
    int* cur;
    cudaGetSymbolAddress((void**)&x,  g_x);
    cudaGetSymbolAddress((void**)&xn, g_xn);
    cudaGetSymbolAddress((void**)&q,  g_q);
    cudaGetSymbolAddress((void**)&k,  g_k);
    cudaGetSymbolAddress((void**)&v,  g_v);
    cudaGetSymbolAddress((void**)&o,  g_o);
    cudaGetSymbolAddress((void**)&ff, g_ff);
    cudaGetSymbolAddress((void**)&cur, g_cur);

    init_k<<<1, 32>>>(start);
    embed_k<<<TOK, Dd>>>(ids, emb, x);

    dim3 gp (Dd/64, TOK/64);          // 8 x 8
    dim3 gf1(Ff/64, TOK/64);          // 32 x 8
    dim3 gf2(Dd/64, TOK/64);
    for (int step = 0; step < 2; step++) {
        rmsnorm_k<<<TOK, Dd>>>(x, n1, cur, xn);
        gemm64<<<gp, 256>>>(xn, Wq, nullptr, q, cur, Dd, Dd, 0);
        gemm64<<<gp, 256>>>(xn, Wk, nullptr, k, cur, Dd, Dd, 0);
        gemm64<<<gp, 256>>>(xn, Wv, nullptr, v, cur, Dd, Dd, 0);
        rope_k<<<TOK, 256>>>(q, k);
        attn_k<<<dim3(Ss, Hh, Bb), 256>>>(q, k, v, o);
        gemm64<<<gp, 256>>>(o, Wo, x, x, cur, Dd, Dd, 1);
        rmsnorm_k<<<TOK, Dd>>>(x, n2, cur, xn);
        gemm64<<<gf1, 256>>>(xn, W1, nullptr, ff, cur, Dd, Ff, 2);
        gemm64<<<gf2, 256>>>(ff, W2, x, x, cur, Ff, Dd, 1);
        gate_k<<<1, 512>>>(x, gw);
    }
    rmsnorm_k<<<TOK, Dd>>>(x, fnw, nullptr, xn);
    gemm64<<<dim3(Vv/64, TOK/64), 256>>>(xn, fcw, nullptr, out, nullptr, Dd, Vv, 0);
    fin_k<<<1, 32>>>(out, out_size);
}

// round 3
// speedup vs baseline: 1.2917x; 1.2917x over previous
#include <cuda_runtime.h>
#include <math.h>

#define Dd  512
#define Hh  8
#define HD  64
#define Bb  2
#define Ss  256
#define Ff  2048
#define Cc  4
#define Vv  32000
#define TOK (Bb*Ss)   // 512

// ---------------- device state (no allocation allowed) ----------------
__device__ float g_x [TOK*Dd];
__device__ float g_xn[TOK*Dd];
__device__ float g_q [TOK*Dd];
__device__ float g_k [TOK*Dd];
__device__ float g_v [TOK*Dd];
__device__ float g_o [TOK*Dd];
__device__ float g_ff[TOK*Ff];
__device__ int   g_cur[Bb];
__device__ float g_accp[Cc+1];
__device__ float g_acclb;

// ---------------- init ----------------
__global__ void init_k(const int* __restrict__ start) {
    if (threadIdx.x == 0) {
        g_cur[0] = start[0];
        g_cur[1] = start[1];
        #pragma unroll
        for (int i = 0; i < Cc+1; i++) g_accp[i] = 0.f;
        g_acclb = 0.f;
    }
}

// ---------------- embedding ----------------
__global__ void embed_k(const int* __restrict__ ids, const float* __restrict__ emb,
                        float* __restrict__ x) {
    int t = blockIdx.x;
    int d = threadIdx.x;
    float scale = sqrtf((float)Dd);
    x[t*Dd + d] = emb[(size_t)ids[t]*Dd + d] * scale;
}

// ---------------- rmsnorm (block per token) ----------------
__global__ void rmsnorm_k(const float* __restrict__ x, const float* __restrict__ w,
                          const int* __restrict__ cur, float* __restrict__ out) {
    int t = blockIdx.x;
    int d = threadIdx.x;          // 512
    __shared__ float red[512];
    float v = x[t*Dd + d];
    red[d] = v*v;
    __syncthreads();
    for (int s = 256; s > 0; s >>= 1) {
        if (d < s) red[d] += red[d+s];
        __syncthreads();
    }
    float scale = rsqrtf(red[0] * (1.0f/Dd) + 1e-6f);
    const float* ww = w;
    if (cur) ww += (size_t)cur[t / Ss] * Dd;
    out[t*Dd + d] = v * scale * ww[d];
}

// ---------------- single-buffered tiled GEMM core ----------------
// Out[M,N] = A[M,K] @ W[K,N], row-major. A stored k-major (transposed) in smem.
// 256 threads. Requires BM*BK % 1024 == 0, BK*BN % 1024 == 0, K % BK == 0,
// (BM/TM)*(BN/TN) == 256.
template<int BM,int BN,int BK,int TM,int TN>
__device__ __forceinline__ void gemm_core(
    const float* __restrict__ A, const float* __restrict__ W,
    int K, int N, int m0, int n0, int tid, float acc[TM][TN])
{
    constexpr int AST = BM + 4;
    __shared__ __align__(16) float As[BK][AST];   // As[k][m]
    __shared__ __align__(16) float Bs[BK][BN];    // Bs[k][n]
    constexpr int A_F4 = BM*BK/1024;              // float4 loads per thread
    constexpr int B_F4 = BK*BN/1024;
    constexpr int AKW  = BK/4;                    // float4 per A row
    constexpr int BNW  = BN/4;                    // float4 per B row
    const int ty = tid / (BN/TN), tx = tid % (BN/TN);

    for (int k0 = 0; k0 < K; k0 += BK) {
        #pragma unroll
        for (int l = 0; l < A_F4; l++) {
            int idx = tid + l*256;
            int row = idx / AKW;
            int kc  = (idx % AKW)*4;
            float4 pa = *(const float4*)&A[(size_t)(m0+row)*K + k0 + kc];
            As[kc+0][row] = pa.x; As[kc+1][row] = pa.y;
            As[kc+2][row] = pa.z; As[kc+3][row] = pa.w;
        }
        #pragma unroll
        for (int l = 0; l < B_F4; l++) {
            int idx = tid + l*256;
            int kr = idx / BNW;
            int nc = (idx % BNW)*4;
            *(float4*)&Bs[kr][nc] = *(const float4*)&W[(size_t)(k0+kr)*N + n0 + nc];
        }
        __syncthreads();
        #pragma unroll
        for (int kk = 0; kk < BK; kk++) {
            float a[TM], b[TN];
            #pragma unroll
            for (int i = 0; i < TM; i += 4)
                *(float4*)&a[i] = *(const float4*)&As[kk][ty*TM+i];
            #pragma unroll
            for (int j = 0; j < TN; j += 4)
                *(float4*)&b[j] = *(const float4*)&Bs[kk][tx*TN+j];
            #pragma unroll
            for (int i = 0; i < TM; i++)
                #pragma unroll
                for (int j = 0; j < TN; j++)
                    acc[i][j] = fmaf(a[i], b[j], acc[i][j]);
        }
        __syncthreads();
    }
}

// ---------------- big GEMM (logits): 128x128x32 tiles, 8x8/thread ----------------
__global__ void __launch_bounds__(256,2) gemm_big(
    const float* __restrict__ A, const float* __restrict__ W,
    float* __restrict__ Out, int K, int N)
{
    float acc[8][8] = {};
    int m0 = blockIdx.y*128, n0 = blockIdx.x*128;
    gemm_core<128,128,32,8,8>(A, W, K, N, m0, n0, threadIdx.x, acc);
    int ty = threadIdx.x/16, tx = threadIdx.x%16;
    #pragma unroll
    for (int i = 0; i < 8; i++) {
        size_t row = (size_t)(m0 + ty*8 + i)*N + n0 + tx*8;
        *(float4*)&Out[row]   = *(float4*)&acc[i][0];
        *(float4*)&Out[row+4] = *(float4*)&acc[i][4];
    }
}

// ---------------- mid GEMM: 64x64x32 tiles, 4x4/thread ----------------
// epi: 0 = store, 1 = res + acc, 2 = silu(acc)
__global__ void __launch_bounds__(256) gemm_mid(
    const float* __restrict__ A, const float* __restrict__ Wb,
    const float* __restrict__ res, float* __restrict__ Out,
    const int* __restrict__ cur, int K, int N, int epi)
{
    int m0 = blockIdx.y*64, n0 = blockIdx.x*64;
    const float* W = Wb;
    if (cur) W += (size_t)cur[m0 / Ss] * K * N;

    float acc[4][4] = {};
    gemm_core<64,64,32,4,4>(A, W, K, N, m0, n0, threadIdx.x, acc);

    int ty = threadIdx.x/16, tx = threadIdx.x%16;
    #pragma unroll
    for (int i = 0; i < 4; i++) {
        size_t row = (size_t)(m0 + ty*4 + i)*N + n0 + tx*4;
        float4 r = *(float4*)&acc[i][0];
        if (epi == 1) {
            float4 rr = *(const float4*)&res[row];
            r.x += rr.x; r.y += rr.y; r.z += rr.z; r.w += rr.w;
        } else if (epi == 2) {
            r.x = r.x / (1.f + expf(-r.x));
            r.y = r.y / (1.f + expf(-r.y));
            r.z = r.z / (1.f + expf(-r.z));
            r.w = r.w / (1.f + expf(-r.w));
        }
        *(float4*)&Out[row] = r;
    }
}

// ---------------- fused QKV (no rope): grid.z = 0(q),1(k),2(v) ----------------
__global__ void __launch_bounds__(256) qkv_k(
    const float* __restrict__ xn,
    const float* __restrict__ Wq, const float* __restrict__ Wk, const float* __restrict__ Wv,
    float* __restrict__ q, float* __restrict__ k, float* __restrict__ v,
    const int* __restrict__ cur)
{
    int z = blockIdx.z;
    const float* Wb = (z == 0) ? Wq : (z == 1) ? Wk : Wv;
    float* O = (z == 0) ? q : (z == 1) ? k : v;
    int m0 = blockIdx.y*64, n0 = blockIdx.x*64;
    const float* W = Wb + (size_t)cur[m0 / Ss] * Dd * Dd;

    float acc[4][4] = {};
    gemm_core<64,64,32,4,4>(xn, W, Dd, Dd, m0, n0, threadIdx.x, acc);

    int ty = threadIdx.x/16, tx = threadIdx.x%16;
    #pragma unroll
    for (int i = 0; i < 4; i++) {
        int m = m0 + ty*4 + i;
        *(float4*)&O[(size_t)m*Dd + n0 + tx*4] = *(float4*)&acc[i][0];
    }
}

// ---------------- rope on q,k (R1-verbatim, known good) ----------------
__global__ void rope_k(float* __restrict__ q, float* __restrict__ k) {
    int t = blockIdx.x;               // token
    int s = t % Ss;                   // position
    int i = threadIdx.x;              // 0..255 pair index in D
    int h = i >> 5;                   // head (32 pairs/head)
    int j = i & 31;
    float inv = powf(10000.f, -(2.f*j) / 64.f);
    float ang = (float)s * inv;
    float c = cosf(ang), sn = sinf(ang);
    int base = t*Dd + h*HD + 2*j;
    float q1 = q[base], q2 = q[base+1];
    q[base]   = q1*c - q2*sn;
    q[base+1] = q1*sn + q2*c;
    float k1 = k[base], k2 = k[base+1];
    k[base]   = k1*c - k2*sn;
    k[base+1] = k1*sn + k2*c;
}

// ---------------- causal attention: block per (b,h,q-row) ----------------
__global__ void attn_k(const float* __restrict__ q, const float* __restrict__ k,
                       const float* __restrict__ v, float* __restrict__ o) {
    int qi = blockIdx.x, h = blockIdx.y, b = blockIdx.z;
    int tid = threadIdx.x;            // 256
    __shared__ float qv[HD];
    __shared__ float p[Ss];
    __shared__ float red[Ss];
    int base_bh = b*Ss*Dd + h*HD;
    if (tid < HD) qv[tid] = q[base_bh + qi*Dd + tid];
    __syncthreads();

    float s;
    if (tid <= qi) {
        const float* kp = &k[base_bh + tid*Dd];
        s = 0.f;
        #pragma unroll
        for (int d2 = 0; d2 < HD; d2++) s += qv[d2] * kp[d2];
        s *= 0.125f;
    } else {
        s = -1e30f;
    }
    red[tid] = s; __syncthreads();
    for (int st = 128; st > 0; st >>= 1) {
        if (tid < st) red[tid] = fmaxf(red[tid], red[tid+st]);
        __syncthreads();
    }
    float mx = red[0];
    __syncthreads();
    float e = expf(s - mx);
    p[tid] = e;
    red[tid] = e; __syncthreads();
    for (int st = 128; st > 0; st >>= 1) {
        if (tid < st) red[tid] += red[tid+st];
        __syncthreads();
    }
    float inv = 1.f / red[0];
    __syncthreads();
    if (tid < HD) {
        float acc = 0.f;
        for (int t2 = 0; t2 <= qi; t2++)
            acc += p[t2] * v[base_bh + t2*Dd + tid];
        o[base_bh + qi*Dd + tid] = acc * inv;
    }
}

// ---------------- gating + routing (single block) ----------------
__global__ void gate_k(const float* __restrict__ x, const float* __restrict__ gw) {
    __shared__ float pooled[Bb][Dd];
    __shared__ float red[512];
    __shared__ float sc[2*(Cc+1)];
    int tid = threadIdx.x;            // 512
    for (int b = 0; b < Bb; b++) {
        float s = 0.f;
        for (int ss = 0; ss < Ss; ss++) s += x[(size_t)(b*Ss+ss)*Dd + tid];
        pooled[b][tid] = s * (1.f/Ss);
    }
    __syncthreads();
    for (int idx = 0; idx < 2*(Cc+1); idx++) {
        int b = idx / (Cc+1), c = idx % (Cc+1);
        red[tid] = pooled[b][tid] * gw[tid*(Cc+1) + c];
        __syncthreads();
        for (int s = 256; s > 0; s >>= 1) {
            if (tid < s) red[tid] += red[tid+s];
            __syncthreads();
        }
        if (tid == 0) sc[idx] = red[0];
        __syncthreads();
    }
    if (tid == 0) {
        float p[Bb][Cc+1];
        for (int b = 0; b < Bb; b++) {
            float mx = -1e30f;
            for (int c = 0; c < Cc+1; c++) mx = fmaxf(mx, sc[b*(Cc+1)+c]);
            float sum = 0.f;
            for (int c = 0; c < Cc+1; c++) { p[b][c] = expf(sc[b*(Cc+1)+c] - mx); sum += p[b][c]; }
            for (int c = 0; c < Cc+1; c++) p[b][c] /= sum;
        }
        float lb = 0.f;
        for (int c = 0; c < Cc+1; c++) {
            g_accp[c] += p[0][c] + p[1][c];
            float avg = 0.5f * (p[0][c] + p[1][c]);
            lb += avg*avg;
        }
        g_acclb += (float)(Cc+1) * lb;
        for (int b = 0; b < Bb; b++) {
            int co = g_cur[b];
            int j1 = (co+1) & 3, j2 = (co+2) & 3;
            float s1 = sc[b*(Cc+1)+j1], s2 = sc[b*(Cc+1)+j2];
            int w;
            if (s1 > s2) w = j1;
            else if (s2 > s1) w = j2;
            else w = (j1 < j2) ? j1 : j2;
            g_cur[b] = w;
        }
    }
}

// ---------------- finalize aux losses ----------------
__global__ void fin_k(float* __restrict__ out, int n) {
    if (threadIdx.x == 0) {
        float avg[Cc+1];
        float m = 0.f;
        for (int i = 0; i < Cc+1; i++) { avg[i] = g_accp[i] * 0.25f; m += avg[i]; }
        m *= 1.f/(Cc+1);
        float var = 0.f;
        for (int i = 0; i < Cc+1; i++) { float d = avg[i] - m; var += d*d; }
        var *= 1.f/(Cc+1);
        out[n-2] = var;
        out[n-1] = g_acclb * 0.5f;
    }
}

// ---------------- host orchestration ----------------
extern "C" void kernel_launch(void* const* d_in, const int* in_sizes, int n_in,
                              void* d_out, int out_size) {
    const int*   ids   = (const int*)  d_in[0];
    const int*   start = (const int*)  d_in[1];
    const float* emb   = (const float*)d_in[2];
    const float* Wq    = (const float*)d_in[3];
    const float* Wk    = (const float*)d_in[4];
    const float* Wv    = (const float*)d_in[5];
    const float* Wo    = (const float*)d_in[6];
    const float* W1    = (const float*)d_in[7];
    const float* W2    = (const float*)d_in[8];
    const float* n1    = (const float*)d_in[9];
    const float* n2    = (const float*)d_in[10];
    const float* gw    = (const float*)d_in[11];
    const float* fnw   = (const float*)d_in[12];
    const float* fcw   = (const float*)d_in[13];
    float* out = (float*)d_out;

    float *x, *xn, *q, *k, *v, *o, *ff;
    int* cur;
    cudaGetSymbolAddress((void**)&x,  g_x);
    cudaGetSymbolAddress((void**)&xn, g_xn);
    cudaGetSymbolAddress((void**)&q,  g_q);
    cudaGetSymbolAddress((void**)&k,  g_k);
    cudaGetSymbolAddress((void**)&v,  g_v);
    cudaGetSymbolAddress((void**)&o,  g_o);
    cudaGetSymbolAddress((void**)&ff, g_ff);
    cudaGetSymbolAddress((void**)&cur, g_cur);

    init_k<<<1, 32>>>(start);
    embed_k<<<TOK, Dd>>>(ids, emb, x);

    dim3 gqkv(Dd/64, TOK/64, 3);      // 8 x 8 x 3 = 192 blocks
    dim3 gwo (Dd/64, TOK/64);
    dim3 gw1 (Ff/64, TOK/64);         // 32 x 8
    dim3 gw2 (Dd/64, TOK/64);
    for (int step = 0; step < 2; step++) {
        rmsnorm_k<<<TOK, Dd>>>(x, n1, cur, xn);
        qkv_k<<<gqkv, 256>>>(xn, Wq, Wk, Wv, q, k, v, cur);
        rope_k<<<TOK, 256>>>(q, k);
        attn_k<<<dim3(Ss, Hh, Bb), 256>>>(q, k, v, o);
        gemm_mid<<<gwo, 256>>>(o, Wo, x, x, cur, Dd, Dd, 1);
        rmsnorm_k<<<TOK, Dd>>>(x, n2, cur, xn);
        gemm_mid<<<gw1, 256>>>(xn, W1, nullptr, ff, cur, Dd, Ff, 2);
        gemm_mid<<<gw2, 256>>>(ff, W2, x, x, cur, Ff, Dd, 1);
        gate_k<<<1, 512>>>(x, gw);
    }
    rmsnorm_k<<<TOK, Dd>>>(x, fnw, nullptr, xn);
    gemm_big<<<dim3(Vv/128, TOK/128), 256>>>(xn, fcw, out, Dd, Vv);
    fin_k<<<1, 32>>>(out, out_size);
}

// round 4
// speedup vs baseline: 1.6283x; 1.2606x over previous
#include <cuda_runtime.h>
#include <math.h>
#include <stdint.h>

#define Dd  512
#define Hh  8
#define HD  64
#define Bb  2
#define Ss  256
#define Ff  2048
#define Cc  4
#define Vv  32000
#define TOK (Bb*Ss)   // 512

// ---------------- device state (no allocation allowed) ----------------
__device__ float g_x [TOK*Dd];
__device__ float g_xn[TOK*Dd];
__device__ float g_q [TOK*Dd];
__device__ float g_k [TOK*Dd];
__device__ float g_v [TOK*Dd];
__device__ float g_o [TOK*Dd];
__device__ float g_ff[TOK*Ff];
__device__ int   g_cur[Bb];
__device__ float g_accp[Cc+1];
__device__ float g_acclb;

// ---------------- init ----------------
__global__ void init_k(const int* __restrict__ start) {
    if (threadIdx.x == 0) {
        g_cur[0] = start[0];
        g_cur[1] = start[1];
        #pragma unroll
        for (int i = 0; i < Cc+1; i++) g_accp[i] = 0.f;
        g_acclb = 0.f;
    }
}

// ---------------- embedding ----------------
__global__ void embed_k(const int* __restrict__ ids, const float* __restrict__ emb,
                        float* __restrict__ x) {
    int t = blockIdx.x;
    int d = threadIdx.x;
    float scale = sqrtf((float)Dd);
    x[t*Dd + d] = emb[(size_t)ids[t]*Dd + d] * scale;
}

// ---------------- rmsnorm (block per token) ----------------
__global__ void rmsnorm_k(const float* __restrict__ x, const float* __restrict__ w,
                          const int* __restrict__ cur, float* __restrict__ out) {
    int t = blockIdx.x;
    int d = threadIdx.x;          // 512
    __shared__ float red[512];
    float v = x[t*Dd + d];
    red[d] = v*v;
    __syncthreads();
    for (int s = 256; s > 0; s >>= 1) {
        if (d < s) red[d] += red[d+s];
        __syncthreads();
    }
    float scale = rsqrtf(red[0] * (1.0f/Dd) + 1e-6f);
    const float* ww = w;
    if (cur) ww += (size_t)cur[t / Ss] * Dd;
    out[t*Dd + d] = v * scale * ww[d];
}

// ---------------- tf32 helpers ----------------
__device__ __forceinline__ uint32_t f2tf32(float f) {
    uint32_t u;
    asm volatile("cvt.rna.tf32.f32 %0, %1;" : "=r"(u) : "f"(f));
    return u;
}

__device__ __forceinline__ void mma_tf32(float c[4],
    uint32_t a0, uint32_t a1, uint32_t a2, uint32_t a3,
    uint32_t b0, uint32_t b1)
{
    asm volatile(
        "mma.sync.aligned.m16n8k8.row.col.f32.tf32.tf32.f32 "
        "{%0,%1,%2,%3}, {%4,%5,%6,%7}, {%8,%9}, {%0,%1,%2,%3};"
        : "+f"(c[0]), "+f"(c[1]), "+f"(c[2]), "+f"(c[3])
        : "r"(a0), "r"(a1), "r"(a2), "r"(a3), "r"(b0), "r"(b1));
}

// ---------------- tensor-core logits GEMM: Out[M,N] = A[M,K] @ W[K,N] ----------------
// 128x128 block tile, BK=32, 256 threads = 8 warps in 2(m) x 4(n), warp tile 64x32.
__global__ void __launch_bounds__(256,2) gemm_tc(
    const float* __restrict__ A, const float* __restrict__ W,
    float* __restrict__ Out, int K, int N)
{
    constexpr int KST = 36;   // As row stride (words)
    constexpr int NST = 136;  // Bs row stride (words)
    __shared__ uint32_t As[128][KST];  // [m][k] tf32 bits
    __shared__ uint32_t Bs[32][NST];   // [k][n]
    int tid = threadIdx.x;
    int m0 = blockIdx.x*128, n0 = blockIdx.y*128;
    int warp = tid >> 5, lane = tid & 31;
    int wm = warp & 1, wn = warp >> 1;       // 2 x 4
    int g = lane >> 2, tg = lane & 3;

    float acc[4][4][4] = {};                  // [mt][nt][c0..c3]

    for (int k0 = 0; k0 < K; k0 += 32) {
        // fill A tile (128 x 32)
        #pragma unroll
        for (int l = 0; l < 4; l++) {
            int idx = tid + l*256;
            int row = idx >> 3;
            int kc  = (idx & 7) * 4;
            float4 pa = *(const float4*)&A[(size_t)(m0+row)*K + k0 + kc];
            uint4 ua = { f2tf32(pa.x), f2tf32(pa.y), f2tf32(pa.z), f2tf32(pa.w) };
            *(uint4*)&As[row][kc] = ua;
        }
        // fill B tile (32 x 128)
        #pragma unroll
        for (int l = 0; l < 4; l++) {
            int idx = tid + l*256;
            int kr = idx >> 5;
            int nc = (idx & 31) * 4;
            float4 pb = *(const float4*)&W[(size_t)(k0+kr)*N + n0 + nc];
            uint4 ub = { f2tf32(pb.x), f2tf32(pb.y), f2tf32(pb.z), f2tf32(pb.w) };
            *(uint4*)&Bs[kr][nc] = ub;
        }
        __syncthreads();

        #pragma unroll
        for (int kk = 0; kk < 32; kk += 8) {
            uint32_t af[4][4], bf[4][2];
            #pragma unroll
            for (int mt = 0; mt < 4; mt++) {
                int mrow = wm*64 + mt*16 + g;
                af[mt][0] = As[mrow  ][kk+tg];
                af[mt][1] = As[mrow+8][kk+tg];
                af[mt][2] = As[mrow  ][kk+tg+4];
                af[mt][3] = As[mrow+8][kk+tg+4];
            }
            #pragma unroll
            for (int nt = 0; nt < 4; nt++) {
                int ncol = wn*32 + nt*8 + g;
                bf[nt][0] = Bs[kk+tg  ][ncol];
                bf[nt][1] = Bs[kk+tg+4][ncol];
            }
            #pragma unroll
            for (int mt = 0; mt < 4; mt++)
                #pragma unroll
                for (int nt = 0; nt < 4; nt++)
                    mma_tf32(acc[mt][nt], af[mt][0], af[mt][1], af[mt][2], af[mt][3],
                             bf[nt][0], bf[nt][1]);
        }
        __syncthreads();
    }

    // epilogue: c0 (g, 2tg), c1 (g, 2tg+1), c2 (g+8, 2tg), c3 (g+8, 2tg+1)
    #pragma unroll
    for (int mt = 0; mt < 4; mt++) {
        #pragma unroll
        for (int nt = 0; nt < 4; nt++) {
            int row = m0 + wm*64 + mt*16 + g;
            int col = n0 + wn*32 + nt*8 + 2*tg;
            float2 lo = { acc[mt][nt][0], acc[mt][nt][1] };
            float2 hi = { acc[mt][nt][2], acc[mt][nt][3] };
            *(float2*)&Out[(size_t)row*N + col]     = lo;
            *(float2*)&Out[(size_t)(row+8)*N + col] = hi;
        }
    }
}

// ---------------- single-buffered tiled GEMM core (fp32 SIMT, verified) ----------------
template<int BM,int BN,int BK,int TM,int TN>
__device__ __forceinline__ void gemm_core(
    const float* __restrict__ A, const float* __restrict__ W,
    int K, int N, int m0, int n0, int tid, float acc[TM][TN])
{
    constexpr int AST = BM + 4;
    __shared__ __align__(16) float As[BK][AST];   // As[k][m]
    __shared__ __align__(16) float Bs[BK][BN];    // Bs[k][n]
    constexpr int A_F4 = BM*BK/1024;
    constexpr int B_F4 = BK*BN/1024;
    constexpr int AKW  = BK/4;
    constexpr int BNW  = BN/4;
    const int ty = tid / (BN/TN), tx = tid % (BN/TN);

    for (int k0 = 0; k0 < K; k0 += BK) {
        #pragma unroll
        for (int l = 0; l < A_F4; l++) {
            int idx = tid + l*256;
            int row = idx / AKW;
            int kc  = (idx % AKW)*4;
            float4 pa = *(const float4*)&A[(size_t)(m0+row)*K + k0 + kc];
            As[kc+0][row] = pa.x; As[kc+1][row] = pa.y;
            As[kc+2][row] = pa.z; As[kc+3][row] = pa.w;
        }
        #pragma unroll
        for (int l = 0; l < B_F4; l++) {
            int idx = tid + l*256;
            int kr = idx / BNW;
            int nc = (idx % BNW)*4;
            *(float4*)&Bs[kr][nc] = *(const float4*)&W[(size_t)(k0+kr)*N + n0 + nc];
        }
        __syncthreads();
        #pragma unroll
        for (int kk = 0; kk < BK; kk++) {
            float a[TM], b[TN];
            #pragma unroll
            for (int i = 0; i < TM; i += 4)
                *(float4*)&a[i] = *(const float4*)&As[kk][ty*TM+i];
            #pragma unroll
            for (int j = 0; j < TN; j += 4)
                *(float4*)&b[j] = *(const float4*)&Bs[kk][tx*TN+j];
            #pragma unroll
            for (int i = 0; i < TM; i++)
                #pragma unroll
                for (int j = 0; j < TN; j++)
                    acc[i][j] = fmaf(a[i], b[j], acc[i][j]);
        }
        __syncthreads();
    }
}

// ---------------- mid GEMM: 64x64x32 tiles, 4x4/thread ----------------
// epi: 0 = store, 1 = res + acc, 2 = silu(acc)
__global__ void __launch_bounds__(256) gemm_mid(
    const float* __restrict__ A, const float* __restrict__ Wb,
    const float* __restrict__ res, float* __restrict__ Out,
    const int* __restrict__ cur, int K, int N, int epi)
{
    int m0 = blockIdx.y*64, n0 = blockIdx.x*64;
    const float* W = Wb;
    if (cur) W += (size_t)cur[m0 / Ss] * K * N;

    float acc[4][4] = {};
    gemm_core<64,64,32,4,4>(A, W, K, N, m0, n0, threadIdx.x, acc);

    int ty = threadIdx.x/16, tx = threadIdx.x%16;
    #pragma unroll
    for (int i = 0; i < 4; i++) {
        size_t row = (size_t)(m0 + ty*4 + i)*N + n0 + tx*4;
        float4 r = *(float4*)&acc[i][0];
        if (epi == 1) {
            float4 rr = *(const float4*)&res[row];
            r.x += rr.x; r.y += rr.y; r.z += rr.z; r.w += rr.w;
        } else if (epi == 2) {
            r.x = r.x / (1.f + expf(-r.x));
            r.y = r.y / (1.f + expf(-r.y));
            r.z = r.z / (1.f + expf(-r.z));
            r.w = r.w / (1.f + expf(-r.w));
        }
        *(float4*)&Out[row] = r;
    }
}

// ---------------- fused QKV (no rope): grid.z = 0(q),1(k),2(v) ----------------
__global__ void __launch_bounds__(256) qkv_k(
    const float* __restrict__ xn,
    const float* __restrict__ Wq, const float* __restrict__ Wk, const float* __restrict__ Wv,
    float* __restrict__ q, float* __restrict__ k, float* __restrict__ v,
    const int* __restrict__ cur)
{
    int z = blockIdx.z;
    const float* Wb = (z == 0) ? Wq : (z == 1) ? Wk : Wv;
    float* O = (z == 0) ? q : (z == 1) ? k : v;
    int m0 = blockIdx.y*64, n0 = blockIdx.x*64;
    const float* W = Wb + (size_t)cur[m0 / Ss] * Dd * Dd;

    float acc[4][4] = {};
    gemm_core<64,64,32,4,4>(xn, W, Dd, Dd, m0, n0, threadIdx.x, acc);

    int ty = threadIdx.x/16, tx = threadIdx.x%16;
    #pragma unroll
    for (int i = 0; i < 4; i++) {
        int m = m0 + ty*4 + i;
        *(float4*)&O[(size_t)m*Dd + n0 + tx*4] = *(float4*)&acc[i][0];
    }
}

// ---------------- rope on q,k ----------------
__global__ void rope_k(float* __restrict__ q, float* __restrict__ k) {
    int t = blockIdx.x;
    int s = t % Ss;
    int i = threadIdx.x;
    int h = i >> 5;
    int j = i & 31;
    float inv = powf(10000.f, -(2.f*j) / 64.f);
    float ang = (float)s * inv;
    float c = cosf(ang), sn = sinf(ang);
    int base = t*Dd + h*HD + 2*j;
    float q1 = q[base], q2 = q[base+1];
    q[base]   = q1*c - q2*sn;
    q[base+1] = q1*sn + q2*c;
    float k1 = k[base], k2 = k[base+1];
    k[base]   = k1*c - k2*sn;
    k[base+1] = k1*sn + k2*c;
}

// ---------------- causal attention: block per (b,h,q-row) ----------------
__global__ void attn_k(const float* __restrict__ q, const float* __restrict__ k,
                       const float* __restrict__ v, float* __restrict__ o) {
    int qi = blockIdx.x, h = blockIdx.y, b = blockIdx.z;
    int tid = threadIdx.x;            // 256
    __shared__ float qv[HD];
    __shared__ float p[Ss];
    __shared__ float red[Ss];
    int base_bh = b*Ss*Dd + h*HD;
    if (tid < HD) qv[tid] = q[base_bh + qi*Dd + tid];
    __syncthreads();

    float s;
    if (tid <= qi) {
        const float* kp = &k[base_bh + tid*Dd];
        s = 0.f;
        #pragma unroll
        for (int d2 = 0; d2 < HD; d2++) s += qv[d2] * kp[d2];
        s *= 0.125f;
    } else {
        s = -1e30f;
    }
    red[tid] = s; __syncthreads();
    for (int st = 128; st > 0; st >>= 1) {
        if (tid < st) red[tid] = fmaxf(red[tid], red[tid+st]);
        __syncthreads();
    }
    float mx = red[0];
    __syncthreads();
    float e = expf(s - mx);
    p[tid] = e;
    red[tid] = e; __syncthreads();
    for (int st = 128; st > 0; st >>= 1) {
        if (tid < st) red[tid] += red[tid+st];
        __syncthreads();
    }
    float inv = 1.f / red[0];
    __syncthreads();
    if (tid < HD) {
        float acc = 0.f;
        for (int t2 = 0; t2 <= qi; t2++)
            acc += p[t2] * v[base_bh + t2*Dd + tid];
        o[base_bh + qi*Dd + tid] = acc * inv;
    }
}

// ---------------- gating + routing (single block) ----------------
__global__ void gate_k(const float* __restrict__ x, const float* __restrict__ gw) {
    __shared__ float pooled[Bb][Dd];
    __shared__ float red[512];
    __shared__ float sc[2*(Cc+1)];
    int tid = threadIdx.x;            // 512
    for (int b = 0; b < Bb; b++) {
        float s = 0.f;
        for (int ss = 0; ss < Ss; ss++) s += x[(size_t)(b*Ss+ss)*Dd + tid];
        pooled[b][tid] = s * (1.f/Ss);
    }
    __syncthreads();
    for (int idx = 0; idx < 2*(Cc+1); idx++) {
        int b = idx / (Cc+1), c = idx % (Cc+1);
        red[tid] = pooled[b][tid] * gw[tid*(Cc+1) + c];
        __syncthreads();
        for (int s = 256; s > 0; s >>= 1) {
            if (tid < s) red[tid] += red[tid+s];
            __syncthreads();
        }
        if (tid == 0) sc[idx] = red[0];
        __syncthreads();
    }
    if (tid == 0) {
        float p[Bb][Cc+1];
        for (int b = 0; b < Bb; b++) {
            float mx = -1e30f;
            for (int c = 0; c < Cc+1; c++) mx = fmaxf(mx, sc[b*(Cc+1)+c]);
            float sum = 0.f;
            for (int c = 0; c < Cc+1; c++) { p[b][c] = expf(sc[b*(Cc+1)+c] - mx); sum += p[b][c]; }
            for (int c = 0; c < Cc+1; c++) p[b][c] /= sum;
        }
        float lb = 0.f;
        for (int c = 0; c < Cc+1; c++) {
            g_accp[c] += p[0][c] + p[1][c];
            float avg = 0.5f * (p[0][c] + p[1][c]);
            lb += avg*avg;
        }
        g_acclb += (float)(Cc+1) * lb;
        for (int b = 0; b < Bb; b++) {
            int co = g_cur[b];
            int j1 = (co+1) & 3, j2 = (co+2) & 3;
            float s1 = sc[b*(Cc+1)+j1], s2 = sc[b*(Cc+1)+j2];
            int w;
            if (s1 > s2) w = j1;
            else if (s2 > s1) w = j2;
            else w = (j1 < j2) ? j1 : j2;
            g_cur[b] = w;
        }
    }
}

// ---------------- finalize aux losses ----------------
__global__ void fin_k(float* __restrict__ out, int n) {
    if (threadIdx.x == 0) {
        float avg[Cc+1];
        float m = 0.f;
        for (int i = 0; i < Cc+1; i++) { avg[i] = g_accp[i] * 0.25f; m += avg[i]; }
        m *= 1.f/(Cc+1);
        float var = 0.f;
        for (int i = 0; i < Cc+1; i++) { float d = avg[i] - m; var += d*d; }
        var *= 1.f/(Cc+1);
        out[n-2] = var;
        out[n-1] = g_acclb * 0.5f;
    }
}

// ---------------- host orchestration ----------------
extern "C" void kernel_launch(void* const* d_in, const int* in_sizes, int n_in,
                              void* d_out, int out_size) {
    const int*   ids   = (const int*)  d_in[0];
    const int*   start = (const int*)  d_in[1];
    const float* emb   = (const float*)d_in[2];
    const float* Wq    = (const float*)d_in[3];
    const float* Wk    = (const float*)d_in[4];
    const float* Wv    = (const float*)d_in[5];
    const float* Wo    = (const float*)d_in[6];
    const float* W1    = (const float*)d_in[7];
    const float* W2    = (const float*)d_in[8];
    const float* n1    = (const float*)d_in[9];
    const float* n2    = (const float*)d_in[10];
    const float* gw    = (const float*)d_in[11];
    const float* fnw   = (const float*)d_in[12];
    const float* fcw   = (const float*)d_in[13];
    float* out = (float*)d_out;

    float *x, *xn, *q, *k, *v, *o, *ff;
    int* cur;
    cudaGetSymbolAddress((void**)&x,  g_x);
    cudaGetSymbolAddress((void**)&xn, g_xn);
    cudaGetSymbolAddress((void**)&q,  g_q);
    cudaGetSymbolAddress((void**)&k,  g_k);
    cudaGetSymbolAddress((void**)&v,  g_v);
    cudaGetSymbolAddress((void**)&o,  g_o);
    cudaGetSymbolAddress((void**)&ff, g_ff);
    cudaGetSymbolAddress((void**)&cur, g_cur);

    init_k<<<1, 32>>>(start);
    embed_k<<<TOK, Dd>>>(ids, emb, x);

    dim3 gqkv(Dd/64, TOK/64, 3);
    dim3 gwo (Dd/64, TOK/64);
    dim3 gw1 (Ff/64, TOK/64);
    dim3 gw2 (Dd/64, TOK/64);
    for (int step = 0; step < 2; step++) {
        rmsnorm_k<<<TOK, Dd>>>(x, n1, cur, xn);
        qkv_k<<<gqkv, 256>>>(xn, Wq, Wk, Wv, q, k, v, cur);
        rope_k<<<TOK, 256>>>(q, k);
        attn_k<<<dim3(Ss, Hh, Bb), 256>>>(q, k, v, o);
        gemm_mid<<<gwo, 256>>>(o, Wo, x, x, cur, Dd, Dd, 1);
        rmsnorm_k<<<TOK, Dd>>>(x, n2, cur, xn);
        gemm_mid<<<gw1, 256>>>(xn, W1, nullptr, ff, cur, Dd, Ff, 2);
        gemm_mid<<<gw2, 256>>>(ff, W2, x, x, cur, Ff, Dd, 1);
        gate_k<<<1, 512>>>(x, gw);
    }
    rmsnorm_k<<<TOK, Dd>>>(x, fnw, nullptr, xn);
    gemm_tc<<<dim3(TOK/128, Vv/128), 256>>>(xn, fcw, out, Dd, Vv);
    fin_k<<<1, 32>>>(out, out_size);
}

// round 5
// speedup vs baseline: 1.7358x; 1.0660x over previous
#include <cuda_runtime.h>
#include <math.h>
#include <stdint.h>

#define Dd  512
#define Hh  8
#define HD  64
#define Bb  2
#define Ss  256
#define Ff  2048
#define Cc  4
#define Vv  32000
#define TOK (Bb*Ss)   // 512

// ---------------- device state (no allocation allowed) ----------------
__device__ float g_x [TOK*Dd];
__device__ float g_xn[TOK*Dd];
__device__ float g_q [TOK*Dd];
__device__ float g_k [TOK*Dd];
__device__ float g_v [TOK*Dd];
__device__ float g_o [TOK*Dd];
__device__ float g_ff[TOK*Ff];
__device__ int   g_cur[Bb];
__device__ float g_accp[Cc+1];
__device__ float g_acclb;

// ---------------- init ----------------
__global__ void init_k(const int* __restrict__ start) {
    if (threadIdx.x == 0) {
        g_cur[0] = start[0];
        g_cur[1] = start[1];
        #pragma unroll
        for (int i = 0; i < Cc+1; i++) g_accp[i] = 0.f;
        g_acclb = 0.f;
    }
}

// ---------------- embedding ----------------
__global__ void embed_k(const int* __restrict__ ids, const float* __restrict__ emb,
                        float* __restrict__ x) {
    int t = blockIdx.x;
    int d = threadIdx.x;
    float scale = sqrtf((float)Dd);
    x[t*Dd + d] = emb[(size_t)ids[t]*Dd + d] * scale;
}

// ---------------- rmsnorm (block per token) ----------------
__global__ void rmsnorm_k(const float* __restrict__ x, const float* __restrict__ w,
                          const int* __restrict__ cur, float* __restrict__ out) {
    int t = blockIdx.x;
    int d = threadIdx.x;          // 512
    __shared__ float red[512];
    float v = x[t*Dd + d];
    red[d] = v*v;
    __syncthreads();
    for (int s = 256; s > 0; s >>= 1) {
        if (d < s) red[d] += red[d+s];
        __syncthreads();
    }
    float scale = rsqrtf(red[0] * (1.0f/Dd) + 1e-6f);
    const float* ww = w;
    if (cur) ww += (size_t)cur[t / Ss] * Dd;
    out[t*Dd + d] = v * scale * ww[d];
}

// ---------------- tf32 helpers ----------------
__device__ __forceinline__ uint32_t f2tf32(float f) {
    uint32_t u;
    asm volatile("cvt.rna.tf32.f32 %0, %1;" : "=r"(u) : "f"(f));
    return u;
}

__device__ __forceinline__ void mma_tf32(float c[4],
    uint32_t a0, uint32_t a1, uint32_t a2, uint32_t a3,
    uint32_t b0, uint32_t b1)
{
    asm volatile(
        "mma.sync.aligned.m16n8k8.row.col.f32.tf32.tf32.f32 "
        "{%0,%1,%2,%3}, {%4,%5,%6,%7}, {%8,%9}, {%0,%1,%2,%3};"
        : "+f"(c[0]), "+f"(c[1]), "+f"(c[2]), "+f"(c[3])
        : "r"(a0), "r"(a1), "r"(a2), "r"(a3), "r"(b0), "r"(b1));
}

// split x into hi(tf32) + lo(tf32 of remainder)
__device__ __forceinline__ void tf32_split(float x, uint32_t& hi, uint32_t& lo) {
    hi = f2tf32(x);
    lo = f2tf32(x - __uint_as_float(hi));
}

// ---------------- tensor-core logits GEMM (single-pass tf32, verified R4) ----------------
// 128x128 block tile, BK=32, 256 threads = 8 warps in 2(m) x 4(n), warp tile 64x32.
__global__ void __launch_bounds__(256,2) gemm_tc(
    const float* __restrict__ A, const float* __restrict__ W,
    float* __restrict__ Out, int K, int N)
{
    constexpr int KST = 36;
    constexpr int NST = 136;
    __shared__ uint32_t As[128][KST];  // [m][k]
    __shared__ uint32_t Bs[32][NST];   // [k][n]
    int tid = threadIdx.x;
    int m0 = blockIdx.x*128, n0 = blockIdx.y*128;
    int warp = tid >> 5, lane = tid & 31;
    int wm = warp & 1, wn = warp >> 1;
    int g = lane >> 2, tg = lane & 3;

    float acc[4][4][4] = {};

    for (int k0 = 0; k0 < K; k0 += 32) {
        #pragma unroll
        for (int l = 0; l < 4; l++) {
            int idx = tid + l*256;
            int row = idx >> 3;
            int kc  = (idx & 7) * 4;
            float4 pa = *(const float4*)&A[(size_t)(m0+row)*K + k0 + kc];
            uint4 ua = { f2tf32(pa.x), f2tf32(pa.y), f2tf32(pa.z), f2tf32(pa.w) };
            *(uint4*)&As[row][kc] = ua;
        }
        #pragma unroll
        for (int l = 0; l < 4; l++) {
            int idx = tid + l*256;
            int kr = idx >> 5;
            int nc = (idx & 31) * 4;
            float4 pb = *(const float4*)&W[(size_t)(k0+kr)*N + n0 + nc];
            uint4 ub = { f2tf32(pb.x), f2tf32(pb.y), f2tf32(pb.z), f2tf32(pb.w) };
            *(uint4*)&Bs[kr][nc] = ub;
        }
        __syncthreads();

        #pragma unroll
        for (int kk = 0; kk < 32; kk += 8) {
            uint32_t af[4][4], bf[4][2];
            #pragma unroll
            for (int mt = 0; mt < 4; mt++) {
                int mrow = wm*64 + mt*16 + g;
                af[mt][0] = As[mrow  ][kk+tg];
                af[mt][1] = As[mrow+8][kk+tg];
                af[mt][2] = As[mrow  ][kk+tg+4];
                af[mt][3] = As[mrow+8][kk+tg+4];
            }
            #pragma unroll
            for (int nt = 0; nt < 4; nt++) {
                int ncol = wn*32 + nt*8 + g;
                bf[nt][0] = Bs[kk+tg  ][ncol];
                bf[nt][1] = Bs[kk+tg+4][ncol];
            }
            #pragma unroll
            for (int mt = 0; mt < 4; mt++)
                #pragma unroll
                for (int nt = 0; nt < 4; nt++)
                    mma_tf32(acc[mt][nt], af[mt][0], af[mt][1], af[mt][2], af[mt][3],
                             bf[nt][0], bf[nt][1]);
        }
        __syncthreads();
    }

    #pragma unroll
    for (int mt = 0; mt < 4; mt++) {
        #pragma unroll
        for (int nt = 0; nt < 4; nt++) {
            int row = m0 + wm*64 + mt*16 + g;
            int col = n0 + wn*32 + nt*8 + 2*tg;
            float2 lo = { acc[mt][nt][0], acc[mt][nt][1] };
            float2 hi = { acc[mt][nt][2], acc[mt][nt][3] };
            *(float2*)&Out[(size_t)row*N + col]     = lo;
            *(float2*)&Out[(size_t)(row+8)*N + col] = hi;
        }
    }
}

// ---------------- tf32x3 mid GEMM core: 64x64 block tile, BK=32 ----------------
// 256 threads = 8 warps, 2(m) x 4(n); warp tile 32x16 -> acc[2][2][4].
// Fragment/smem layout identical to gemm_tc (verified), plus lo-compensation.
__device__ __forceinline__ void tc64_core(
    const float* __restrict__ A, const float* __restrict__ W,
    int K, int N, int m0, int n0, int tid, float acc[2][2][4])
{
    constexpr int KST = 36;
    constexpr int NST = 72;
    __shared__ uint32_t Ah[64][KST], Al[64][KST];   // [m][k]
    __shared__ uint32_t Bh[32][NST], Bl[32][NST];   // [k][n]
    int warp = tid >> 5, lane = tid & 31;
    int wm = warp & 1, wn = warp >> 1;
    int g = lane >> 2, tg = lane & 3;

    for (int k0 = 0; k0 < K; k0 += 32) {
        #pragma unroll
        for (int l = 0; l < 2; l++) {
            int idx = tid + l*256;
            int row = idx >> 3;
            int kc  = (idx & 7) * 4;
            float4 pa = *(const float4*)&A[(size_t)(m0+row)*K + k0 + kc];
            uint4 uh, ul;
            tf32_split(pa.x, uh.x, ul.x);
            tf32_split(pa.y, uh.y, ul.y);
            tf32_split(pa.z, uh.z, ul.z);
            tf32_split(pa.w, uh.w, ul.w);
            *(uint4*)&Ah[row][kc] = uh;
            *(uint4*)&Al[row][kc] = ul;
        }
        #pragma unroll
        for (int l = 0; l < 2; l++) {
            int idx = tid + l*256;
            int kr = idx >> 4;
            int nc = (idx & 15) * 4;
            float4 pb = *(const float4*)&W[(size_t)(k0+kr)*N + n0 + nc];
            uint4 uh, ul;
            tf32_split(pb.x, uh.x, ul.x);
            tf32_split(pb.y, uh.y, ul.y);
            tf32_split(pb.z, uh.z, ul.z);
            tf32_split(pb.w, uh.w, ul.w);
            *(uint4*)&Bh[kr][nc] = uh;
            *(uint4*)&Bl[kr][nc] = ul;
        }
        __syncthreads();

        #pragma unroll
        for (int kk = 0; kk < 32; kk += 8) {
            uint32_t ah[2][4], al[2][4], bh[2][2], bl[2][2];
            #pragma unroll
            for (int mt = 0; mt < 2; mt++) {
                int mrow = wm*32 + mt*16 + g;
                ah[mt][0] = Ah[mrow  ][kk+tg];
                ah[mt][1] = Ah[mrow+8][kk+tg];
                ah[mt][2] = Ah[mrow  ][kk+tg+4];
                ah[mt][3] = Ah[mrow+8][kk+tg+4];
                al[mt][0] = Al[mrow  ][kk+tg];
                al[mt][1] = Al[mrow+8][kk+tg];
                al[mt][2] = Al[mrow  ][kk+tg+4];
                al[mt][3] = Al[mrow+8][kk+tg+4];
            }
            #pragma unroll
            for (int nt = 0; nt < 2; nt++) {
                int ncol = wn*16 + nt*8 + g;
                bh[nt][0] = Bh[kk+tg  ][ncol];
                bh[nt][1] = Bh[kk+tg+4][ncol];
                bl[nt][0] = Bl[kk+tg  ][ncol];
                bl[nt][1] = Bl[kk+tg+4][ncol];
            }
            #pragma unroll
            for (int mt = 0; mt < 2; mt++)
                #pragma unroll
                for (int nt = 0; nt < 2; nt++) {
                    mma_tf32(acc[mt][nt], ah[mt][0], ah[mt][1], ah[mt][2], ah[mt][3],
                             bl[nt][0], bl[nt][1]);
                    mma_tf32(acc[mt][nt], al[mt][0], al[mt][1], al[mt][2], al[mt][3],
                             bh[nt][0], bh[nt][1]);
                    mma_tf32(acc[mt][nt], ah[mt][0], ah[mt][1], ah[mt][2], ah[mt][3],
                             bh[nt][0], bh[nt][1]);
                }
        }
        __syncthreads();
    }
}

// shared epilogue for 64x64 tc tiles
__device__ __forceinline__ void tc64_epilogue(
    float acc[2][2][4], const float* __restrict__ res, float* __restrict__ Out,
    int N, int m0, int n0, int tid, int epi)
{
    int warp = tid >> 5, lane = tid & 31;
    int wm = warp & 1, wn = warp >> 1;
    int g = lane >> 2, tg = lane & 3;
    #pragma unroll
    for (int mt = 0; mt < 2; mt++) {
        #pragma unroll
        for (int nt = 0; nt < 2; nt++) {
            int row = m0 + wm*32 + mt*16 + g;
            int col = n0 + wn*16 + nt*8 + 2*tg;
            float2 lo = { acc[mt][nt][0], acc[mt][nt][1] };
            float2 hi = { acc[mt][nt][2], acc[mt][nt][3] };
            if (epi == 1) {
                float2 r0 = *(const float2*)&res[(size_t)row*N + col];
                float2 r1 = *(const float2*)&res[(size_t)(row+8)*N + col];
                lo.x += r0.x; lo.y += r0.y;
                hi.x += r1.x; hi.y += r1.y;
            } else if (epi == 2) {
                lo.x = lo.x / (1.f + expf(-lo.x));
                lo.y = lo.y / (1.f + expf(-lo.y));
                hi.x = hi.x / (1.f + expf(-hi.x));
                hi.y = hi.y / (1.f + expf(-hi.y));
            }
            *(float2*)&Out[(size_t)row*N + col]     = lo;
            *(float2*)&Out[(size_t)(row+8)*N + col] = hi;
        }
    }
}

// ---------------- mid GEMM (tensor core tf32x3) ----------------
// epi: 0 = store, 1 = res + acc, 2 = silu(acc)
__global__ void __launch_bounds__(256) gemm_mid_tc(
    const float* __restrict__ A, const float* __restrict__ Wb,
    const float* __restrict__ res, float* __restrict__ Out,
    const int* __restrict__ cur, int K, int N, int epi)
{
    int m0 = blockIdx.y*64, n0 = blockIdx.x*64;
    const float* W = Wb;
    if (cur) W += (size_t)cur[m0 / Ss] * K * N;
    float acc[2][2][4] = {};
    tc64_core(A, W, K, N, m0, n0, threadIdx.x, acc);
    tc64_epilogue(acc, res, Out, N, m0, n0, threadIdx.x, epi);
}

// ---------------- fused QKV (tensor core tf32x3): grid.z = 0(q),1(k),2(v) ----------------
__global__ void __launch_bounds__(256) qkv_tc(
    const float* __restrict__ xn,
    const float* __restrict__ Wq, const float* __restrict__ Wk, const float* __restrict__ Wv,
    float* __restrict__ q, float* __restrict__ k, float* __restrict__ v,
    const int* __restrict__ cur)
{
    int z = blockIdx.z;
    const float* Wb = (z == 0) ? Wq : (z == 1) ? Wk : Wv;
    float* O = (z == 0) ? q : (z == 1) ? k : v;
    int m0 = blockIdx.y*64, n0 = blockIdx.x*64;
    const float* W = Wb + (size_t)cur[m0 / Ss] * Dd * Dd;
    float acc[2][2][4] = {};
    tc64_core(xn, W, Dd, Dd, m0, n0, threadIdx.x, acc);
    tc64_epilogue(acc, nullptr, O, Dd, m0, n0, threadIdx.x, 0);
}

// ---------------- rope on q,k ----------------
__global__ void rope_k(float* __restrict__ q, float* __restrict__ k) {
    int t = blockIdx.x;
    int s = t % Ss;
    int i = threadIdx.x;
    int h = i >> 5;
    int j = i & 31;
    float inv = powf(10000.f, -(2.f*j) / 64.f);
    float ang = (float)s * inv;
    float c = cosf(ang), sn = sinf(ang);
    int base = t*Dd + h*HD + 2*j;
    float q1 = q[base], q2 = q[base+1];
    q[base]   = q1*c - q2*sn;
    q[base+1] = q1*sn + q2*c;
    float k1 = k[base], k2 = k[base+1];
    k[base]   = k1*c - k2*sn;
    k[base+1] = k1*sn + k2*c;
}

// ---------------- causal attention: block per (b,h,q-row) ----------------
__global__ void attn_k(const float* __restrict__ q, const float* __restrict__ k,
                       const float* __restrict__ v, float* __restrict__ o) {
    int qi = blockIdx.x, h = blockIdx.y, b = blockIdx.z;
    int tid = threadIdx.x;            // 256
    __shared__ float qv[HD];
    __shared__ float p[Ss];
    __shared__ float red[Ss];
    int base_bh = b*Ss*Dd + h*HD;
    if (tid < HD) qv[tid] = q[base_bh + qi*Dd + tid];
    __syncthreads();

    float s;
    if (tid <= qi) {
        const float* kp = &k[base_bh + tid*Dd];
        s = 0.f;
        #pragma unroll
        for (int d2 = 0; d2 < HD; d2++) s += qv[d2] * kp[d2];
        s *= 0.125f;
    } else {
        s = -1e30f;
    }
    red[tid] = s; __syncthreads();
    for (int st = 128; st > 0; st >>= 1) {
        if (tid < st) red[tid] = fmaxf(red[tid], red[tid+st]);
        __syncthreads();
    }
    float mx = red[0];
    __syncthreads();
    float e = expf(s - mx);
    p[tid] = e;
    red[tid] = e; __syncthreads();
    for (int st = 128; st > 0; st >>= 1) {
        if (tid < st) red[tid] += red[tid+st];
        __syncthreads();
    }
    float inv = 1.f / red[0];
    __syncthreads();
    if (tid < HD) {
        float acc = 0.f;
        for (int t2 = 0; t2 <= qi; t2++)
            acc += p[t2] * v[base_bh + t2*Dd + tid];
        o[base_bh + qi*Dd + tid] = acc * inv;
    }
}

// ---------------- gating + routing (single block) ----------------
__global__ void gate_k(const float* __restrict__ x, const float* __restrict__ gw) {
    __shared__ float pooled[Bb][Dd];
    __shared__ float red[512];
    __shared__ float sc[2*(Cc+1)];
    int tid = threadIdx.x;            // 512
    for (int b = 0; b < Bb; b++) {
        float s = 0.f;
        for (int ss = 0; ss < Ss; ss++) s += x[(size_t)(b*Ss+ss)*Dd + tid];
        pooled[b][tid] = s * (1.f/Ss);
    }
    __syncthreads();
    for (int idx = 0; idx < 2*(Cc+1); idx++) {
        int b = idx / (Cc+1), c = idx % (Cc+1);
        red[tid] = pooled[b][tid] * gw[tid*(Cc+1) + c];
        __syncthreads();
        for (int s = 256; s > 0; s >>= 1) {
            if (tid < s) red[tid] += red[tid+s];
            __syncthreads();
        }
        if (tid == 0) sc[idx] = red[0];
        __syncthreads();
    }
    if (tid == 0) {
        float p[Bb][Cc+1];
        for (int b = 0; b < Bb; b++) {
            float mx = -1e30f;
            for (int c = 0; c < Cc+1; c++) mx = fmaxf(mx, sc[b*(Cc+1)+c]);
            float sum = 0.f;
            for (int c = 0; c < Cc+1; c++) { p[b][c] = expf(sc[b*(Cc+1)+c] - mx); sum += p[b][c]; }
            for (int c = 0; c < Cc+1; c++) p[b][c] /= sum;
        }
        float lb = 0.f;
        for (int c = 0; c < Cc+1; c++) {
            g_accp[c] += p[0][c] + p[1][c];
            float avg = 0.5f * (p[0][c] + p[1][c]);
            lb += avg*avg;
        }
        g_acclb += (float)(Cc+1) * lb;
        for (int b = 0; b < Bb; b++) {
            int co = g_cur[b];
            int j1 = (co+1) & 3, j2 = (co+2) & 3;
            float s1 = sc[b*(Cc+1)+j1], s2 = sc[b*(Cc+1)+j2];
            int w;
            if (s1 > s2) w = j1;
            else if (s2 > s1) w = j2;
            else w = (j1 < j2) ? j1 : j2;
            g_cur[b] = w;
        }
    }
}

// ---------------- finalize aux losses ----------------
__global__ void fin_k(float* __restrict__ out, int n) {
    if (threadIdx.x == 0) {
        float avg[Cc+1];
        float m = 0.f;
        for (int i = 0; i < Cc+1; i++) { avg[i] = g_accp[i] * 0.25f; m += avg[i]; }
        m *= 1.f/(Cc+1);
        float var = 0.f;
        for (int i = 0; i < Cc+1; i++) { float d = avg[i] - m; var += d*d; }
        var *= 1.f/(Cc+1);
        out[n-2] = var;
        out[n-1] = g_acclb * 0.5f;
    }
}

// ---------------- host orchestration ----------------
extern "C" void kernel_launch(void* const* d_in, const int* in_sizes, int n_in,
                              void* d_out, int out_size) {
    const int*   ids   = (const int*)  d_in[0];
    const int*   start = (const int*)  d_in[1];
    const float* emb   = (const float*)d_in[2];
    const float* Wq    = (const float*)d_in[3];
    const float* Wk    = (const float*)d_in[4];
    const float* Wv    = (const float*)d_in[5];
    const float* Wo    = (const float*)d_in[6];
    const float* W1    = (const float*)d_in[7];
    const float* W2    = (const float*)d_in[8];
    const float* n1    = (const float*)d_in[9];
    const float* n2    = (const float*)d_in[10];
    const float* gw    = (const float*)d_in[11];
    const float* fnw   = (const float*)d_in[12];
    const float* fcw   = (const float*)d_in[13];
    float* out = (float*)d_out;

    float *x, *xn, *q, *k, *v, *o, *ff;
    int* cur;
    cudaGetSymbolAddress((void**)&x,  g_x);
    cudaGetSymbolAddress((void**)&xn, g_xn);
    cudaGetSymbolAddress((void**)&q,  g_q);
    cudaGetSymbolAddress((void**)&k,  g_k);
    cudaGetSymbolAddress((void**)&v,  g_v);
    cudaGetSymbolAddress((void**)&o,  g_o);
    cudaGetSymbolAddress((void**)&ff, g_ff);
    cudaGetSymbolAddress((void**)&cur, g_cur);

    init_k<<<1, 32>>>(start);
    embed_k<<<TOK, Dd>>>(ids, emb, x);

    dim3 gqkv(Dd/64, TOK/64, 3);
    dim3 gwo (Dd/64, TOK/64);
    dim3 gw1 (Ff/64, TOK/64);
    dim3 gw2 (Dd/64, TOK/64);
    for (int step = 0; step < 2; step++) {
        rmsnorm_k<<<TOK, Dd>>>(x, n1, cur, xn);
        qkv_tc<<<gqkv, 256>>>(xn, Wq, Wk, Wv, q, k, v, cur);
        rope_k<<<TOK, 256>>>(q, k);
        attn_k<<<dim3(Ss, Hh, Bb), 256>>>(q, k, v, o);
        gemm_mid_tc<<<gwo, 256>>>(o, Wo, x, x, cur, Dd, Dd, 1);
        rmsnorm_k<<<TOK, Dd>>>(x, n2, cur, xn);
        gemm_mid_tc<<<gw1, 256>>>(xn, W1, nullptr, ff, cur, Dd, Ff, 2);
        gemm_mid_tc<<<gw2, 256>>>(ff, W2, x, x, cur, Ff, Dd, 1);
        gate_k<<<1, 512>>>(x, gw);
    }
    rmsnorm_k<<<TOK, Dd>>>(x, fnw, nullptr, xn);
    gemm_tc<<<dim3(TOK/128, Vv/128), 256>>>(xn, fcw, out, Dd, Vv);
    fin_k<<<1, 32>>>(out, out_size);
}

// round 6
// speedup vs baseline: 1.8276x; 1.0529x over previous
#include <cuda_runtime.h>
#include <math.h>
#include <stdint.h>

#define Dd  512
#define Hh  8
#define HD  64
#define Bb  2
#define Ss  256
#define Ff  2048
#define Cc  4
#define Vv  32000
#define TOK (Bb*Ss)   // 512

// ---------------- device state (no allocation allowed) ----------------
__device__ float g_x [TOK*Dd];
__device__ float g_xn[TOK*Dd];
__device__ float g_q [TOK*Dd];
__device__ float g_k [TOK*Dd];
__device__ float g_v [TOK*Dd];
__device__ float g_o [TOK*Dd];
__device__ float g_ff[TOK*Ff];
__device__ float g_pool[Bb*Dd];
__device__ int   g_cur[Bb];
__device__ float g_accp[Cc+1];
__device__ float g_acclb;

// ---------------- init ----------------
__global__ void init_k(const int* __restrict__ start) {
    if (threadIdx.x == 0) {
        g_cur[0] = start[0];
        g_cur[1] = start[1];
        #pragma unroll
        for (int i = 0; i < Cc+1; i++) g_accp[i] = 0.f;
        g_acclb = 0.f;
    }
}

// ---------------- embedding ----------------
__global__ void embed_k(const int* __restrict__ ids, const float* __restrict__ emb,
                        float* __restrict__ x) {
    int t = blockIdx.x;
    int d = threadIdx.x;
    float scale = sqrtf((float)Dd);
    x[t*Dd + d] = emb[(size_t)ids[t]*Dd + d] * scale;
}

// ---------------- rmsnorm (block per token) ----------------
__global__ void rmsnorm_k(const float* __restrict__ x, const float* __restrict__ w,
                          const int* __restrict__ cur, float* __restrict__ out) {
    int t = blockIdx.x;
    int d = threadIdx.x;          // 512
    __shared__ float red[512];
    float v = x[t*Dd + d];
    red[d] = v*v;
    __syncthreads();
    for (int s = 256; s > 0; s >>= 1) {
        if (d < s) red[d] += red[d+s];
        __syncthreads();
    }
    float scale = rsqrtf(red[0] * (1.0f/Dd) + 1e-6f);
    const float* ww = w;
    if (cur) ww += (size_t)cur[t / Ss] * Dd;
    out[t*Dd + d] = v * scale * ww[d];
}

// ---------------- tf32 / cp.async helpers ----------------
__device__ __forceinline__ uint32_t f2tf32(float f) {
    uint32_t u;
    asm volatile("cvt.rna.tf32.f32 %0, %1;" : "=r"(u) : "f"(f));
    return u;
}

__device__ __forceinline__ void mma_tf32(float c[4],
    uint32_t a0, uint32_t a1, uint32_t a2, uint32_t a3,
    uint32_t b0, uint32_t b1)
{
    asm volatile(
        "mma.sync.aligned.m16n8k8.row.col.f32.tf32.tf32.f32 "
        "{%0,%1,%2,%3}, {%4,%5,%6,%7}, {%8,%9}, {%0,%1,%2,%3};"
        : "+f"(c[0]), "+f"(c[1]), "+f"(c[2]), "+f"(c[3])
        : "r"(a0), "r"(a1), "r"(a2), "r"(a3), "r"(b0), "r"(b1));
}

__device__ __forceinline__ void cp_async16(float* smem, const float* gmem) {
    uint32_t s;
    asm("{ .reg .u64 t; cvta.to.shared.u64 t, %1; cvt.u32.u64 %0, t; }"
        : "=r"(s) : "l"(smem));
    asm volatile("cp.async.cg.shared.global [%0], [%1], 16;" :: "r"(s), "l"(gmem) : "memory");
}
#define CP_COMMIT()  asm volatile("cp.async.commit_group;" ::: "memory")
#define CP_WAIT1()   asm volatile("cp.async.wait_group 1;" ::: "memory")
#define CP_WAIT0()   asm volatile("cp.async.wait_group 0;" ::: "memory")

// ---------------- tensor-core logits GEMM (tf32, cp.async double-buffered) ------
// 128x128 block tile, BK=32, 256 threads = 8 warps in 2(m) x 4(n), warp tile 64x32.
// Dynamic smem: As[2][128][36] + Bs[2][32][136]  (raw floats, cvt at fragment read)
#define TC_SMEM ((2*128*36 + 2*32*136) * (int)sizeof(float))
__global__ void __launch_bounds__(256,2) gemm_tc(
    const float* __restrict__ A, const float* __restrict__ W,
    float* __restrict__ Out, int K, int N)
{
    extern __shared__ float dsm[];
    float (*As)[128][36]  = (float(*)[128][36])dsm;
    float (*Bs)[32][136]  = (float(*)[32][136])(dsm + 2*128*36);
    int tid = threadIdx.x;
    int m0 = blockIdx.x*128, n0 = blockIdx.y*128;
    int warp = tid >> 5, lane = tid & 31;
    int wm = warp & 1, wn = warp >> 1;
    int g = lane >> 2, tg = lane & 3;

    auto issue = [&](int k0, int buf) {
        #pragma unroll
        for (int l = 0; l < 4; l++) {
            int idx = tid + l*256;
            int row = idx >> 3, kc = (idx & 7) * 4;
            cp_async16(&As[buf][row][kc], &A[(size_t)(m0+row)*K + k0 + kc]);
        }
        #pragma unroll
        for (int l = 0; l < 4; l++) {
            int idx = tid + l*256;
            int kr = idx >> 5, nc = (idx & 31) * 4;
            cp_async16(&Bs[buf][kr][nc], &W[(size_t)(k0+kr)*N + n0 + nc]);
        }
        CP_COMMIT();
    };

    float acc[4][4][4] = {};
    int nk = K / 32;
    issue(0, 0);
    int buf = 0;
    for (int it = 0; it < nk; it++) {
        bool more = (it + 1) < nk;
        if (more) issue((it+1)*32, buf^1);
        if (more) CP_WAIT1(); else CP_WAIT0();
        __syncthreads();

        #pragma unroll
        for (int kk = 0; kk < 32; kk += 8) {
            uint32_t af[4][4], bf[4][2];
            #pragma unroll
            for (int mt = 0; mt < 4; mt++) {
                int mrow = wm*64 + mt*16 + g;
                af[mt][0] = f2tf32(As[buf][mrow  ][kk+tg]);
                af[mt][1] = f2tf32(As[buf][mrow+8][kk+tg]);
                af[mt][2] = f2tf32(As[buf][mrow  ][kk+tg+4]);
                af[mt][3] = f2tf32(As[buf][mrow+8][kk+tg+4]);
            }
            #pragma unroll
            for (int nt = 0; nt < 4; nt++) {
                int ncol = wn*32 + nt*8 + g;
                bf[nt][0] = f2tf32(Bs[buf][kk+tg  ][ncol]);
                bf[nt][1] = f2tf32(Bs[buf][kk+tg+4][ncol]);
            }
            #pragma unroll
            for (int mt = 0; mt < 4; mt++)
                #pragma unroll
                for (int nt = 0; nt < 4; nt++)
                    mma_tf32(acc[mt][nt], af[mt][0], af[mt][1], af[mt][2], af[mt][3],
                             bf[nt][0], bf[nt][1]);
        }
        __syncthreads();
        buf ^= 1;
    }

    #pragma unroll
    for (int mt = 0; mt < 4; mt++) {
        #pragma unroll
        for (int nt = 0; nt < 4; nt++) {
            int row = m0 + wm*64 + mt*16 + g;
            int col = n0 + wn*32 + nt*8 + 2*tg;
            float2 lo = { acc[mt][nt][0], acc[mt][nt][1] };
            float2 hi = { acc[mt][nt][2], acc[mt][nt][3] };
            *(float2*)&Out[(size_t)row*N + col]     = lo;
            *(float2*)&Out[(size_t)(row+8)*N + col] = hi;
        }
    }
}

// ---------------- tf32x3 mid GEMM core (cp.async double-buffered) ----------------
// 64x64 block tile, BK=32, 256 threads = 8 warps 2(m) x 4(n), warp tile 32x16.
// smem raw floats; hi/lo split at fragment read.
__device__ __forceinline__ void tc64_core(
    const float* __restrict__ A, const float* __restrict__ W,
    int K, int N, int m0, int n0, int tid, float acc[2][2][4])
{
    __shared__ float As[2][64][36];
    __shared__ float Bs[2][32][72];
    int warp = tid >> 5, lane = tid & 31;
    int wm = warp & 1, wn = warp >> 1;
    int g = lane >> 2, tg = lane & 3;

    auto issue = [&](int k0, int buf) {
        #pragma unroll
        for (int l = 0; l < 2; l++) {
            int idx = tid + l*256;
            int row = idx >> 3, kc = (idx & 7) * 4;
            cp_async16(&As[buf][row][kc], &A[(size_t)(m0+row)*K + k0 + kc]);
        }
        #pragma unroll
        for (int l = 0; l < 2; l++) {
            int idx = tid + l*256;
            int kr = idx >> 4, nc = (idx & 15) * 4;
            cp_async16(&Bs[buf][kr][nc], &W[(size_t)(k0+kr)*N + n0 + nc]);
        }
        CP_COMMIT();
    };

    int nk = K / 32;
    issue(0, 0);
    int buf = 0;
    for (int it = 0; it < nk; it++) {
        bool more = (it + 1) < nk;
        if (more) issue((it+1)*32, buf^1);
        if (more) CP_WAIT1(); else CP_WAIT0();
        __syncthreads();

        #pragma unroll
        for (int kk = 0; kk < 32; kk += 8) {
            uint32_t ah[2][4], al[2][4], bh[2][2], bl[2][2];
            #pragma unroll
            for (int mt = 0; mt < 2; mt++) {
                int mrow = wm*32 + mt*16 + g;
                float a0 = As[buf][mrow  ][kk+tg];
                float a1 = As[buf][mrow+8][kk+tg];
                float a2 = As[buf][mrow  ][kk+tg+4];
                float a3 = As[buf][mrow+8][kk+tg+4];
                ah[mt][0] = f2tf32(a0); al[mt][0] = f2tf32(a0 - __uint_as_float(ah[mt][0]));
                ah[mt][1] = f2tf32(a1); al[mt][1] = f2tf32(a1 - __uint_as_float(ah[mt][1]));
                ah[mt][2] = f2tf32(a2); al[mt][2] = f2tf32(a2 - __uint_as_float(ah[mt][2]));
                ah[mt][3] = f2tf32(a3); al[mt][3] = f2tf32(a3 - __uint_as_float(ah[mt][3]));
            }
            #pragma unroll
            for (int nt = 0; nt < 2; nt++) {
                int ncol = wn*16 + nt*8 + g;
                float b0 = Bs[buf][kk+tg  ][ncol];
                float b1 = Bs[buf][kk+tg+4][ncol];
                bh[nt][0] = f2tf32(b0); bl[nt][0] = f2tf32(b0 - __uint_as_float(bh[nt][0]));
                bh[nt][1] = f2tf32(b1); bl[nt][1] = f2tf32(b1 - __uint_as_float(bh[nt][1]));
            }
            #pragma unroll
            for (int mt = 0; mt < 2; mt++)
                #pragma unroll
                for (int nt = 0; nt < 2; nt++) {
                    mma_tf32(acc[mt][nt], ah[mt][0], ah[mt][1], ah[mt][2], ah[mt][3],
                             bl[nt][0], bl[nt][1]);
                    mma_tf32(acc[mt][nt], al[mt][0], al[mt][1], al[mt][2], al[mt][3],
                             bh[nt][0], bh[nt][1]);
                    mma_tf32(acc[mt][nt], ah[mt][0], ah[mt][1], ah[mt][2], ah[mt][3],
                             bh[nt][0], bh[nt][1]);
                }
        }
        __syncthreads();
        buf ^= 1;
    }
}

// shared epilogue for 64x64 tc tiles
__device__ __forceinline__ void tc64_epilogue(
    float acc[2][2][4], const float* __restrict__ res, float* __restrict__ Out,
    int N, int m0, int n0, int tid, int epi)
{
    int warp = tid >> 5, lane = tid & 31;
    int wm = warp & 1, wn = warp >> 1;
    int g = lane >> 2, tg = lane & 3;
    #pragma unroll
    for (int mt = 0; mt < 2; mt++) {
        #pragma unroll
        for (int nt = 0; nt < 2; nt++) {
            int row = m0 + wm*32 + mt*16 + g;
            int col = n0 + wn*16 + nt*8 + 2*tg;
            float2 lo = { acc[mt][nt][0], acc[mt][nt][1] };
            float2 hi = { acc[mt][nt][2], acc[mt][nt][3] };
            if (epi == 1) {
                float2 r0 = *(const float2*)&res[(size_t)row*N + col];
                float2 r1 = *(const float2*)&res[(size_t)(row+8)*N + col];
                lo.x += r0.x; lo.y += r0.y;
                hi.x += r1.x; hi.y += r1.y;
            } else if (epi == 2) {
                lo.x = lo.x / (1.f + expf(-lo.x));
                lo.y = lo.y / (1.f + expf(-lo.y));
                hi.x = hi.x / (1.f + expf(-hi.x));
                hi.y = hi.y / (1.f + expf(-hi.y));
            }
            *(float2*)&Out[(size_t)row*N + col]     = lo;
            *(float2*)&Out[(size_t)(row+8)*N + col] = hi;
        }
    }
}

// ---------------- mid GEMM (tensor core tf32x3) ----------------
__global__ void __launch_bounds__(256) gemm_mid_tc(
    const float* __restrict__ A, const float* __restrict__ Wb,
    const float* __restrict__ res, float* __restrict__ Out,
    const int* __restrict__ cur, int K, int N, int epi)
{
    int m0 = blockIdx.y*64, n0 = blockIdx.x*64;
    const float* W = Wb;
    if (cur) W += (size_t)cur[m0 / Ss] * K * N;
    float acc[2][2][4] = {};
    tc64_core(A, W, K, N, m0, n0, threadIdx.x, acc);
    tc64_epilogue(acc, res, Out, N, m0, n0, threadIdx.x, epi);
}

// ---------------- fused QKV (tensor core tf32x3): grid.z = 0(q),1(k),2(v) ----------------
__global__ void __launch_bounds__(256) qkv_tc(
    const float* __restrict__ xn,
    const float* __restrict__ Wq, const float* __restrict__ Wk, const float* __restrict__ Wv,
    float* __restrict__ q, float* __restrict__ k, float* __restrict__ v,
    const int* __restrict__ cur)
{
    int z = blockIdx.z;
    const float* Wb = (z == 0) ? Wq : (z == 1) ? Wk : Wv;
    float* O = (z == 0) ? q : (z == 1) ? k : v;
    int m0 = blockIdx.y*64, n0 = blockIdx.x*64;
    const float* W = Wb + (size_t)cur[m0 / Ss] * Dd * Dd;
    float acc[2][2][4] = {};
    tc64_core(xn, W, Dd, Dd, m0, n0, threadIdx.x, acc);
    tc64_epilogue(acc, nullptr, O, Dd, m0, n0, threadIdx.x, 0);
}

// ---------------- rope on q,k ----------------
__global__ void rope_k(float* __restrict__ q, float* __restrict__ k) {
    int t = blockIdx.x;
    int s = t % Ss;
    int i = threadIdx.x;
    int h = i >> 5;
    int j = i & 31;
    float inv = powf(10000.f, -(2.f*j) / 64.f);
    float ang = (float)s * inv;
    float c = cosf(ang), sn = sinf(ang);
    int base = t*Dd + h*HD + 2*j;
    float q1 = q[base], q2 = q[base+1];
    q[base]   = q1*c - q2*sn;
    q[base+1] = q1*sn + q2*c;
    float k1 = k[base], k2 = k[base+1];
    k[base]   = k1*c - k2*sn;
    k[base+1] = k1*sn + k2*c;
}

// ---------------- causal attention: block per (b,h,q-row) ----------------
__global__ void attn_k(const float* __restrict__ q, const float* __restrict__ k,
                       const float* __restrict__ v, float* __restrict__ o) {
    int qi = blockIdx.x, h = blockIdx.y, b = blockIdx.z;
    int tid = threadIdx.x;            // 256
    __shared__ float qv[HD];
    __shared__ float p[Ss];
    __shared__ float red[Ss];
    int base_bh = b*Ss*Dd + h*HD;
    if (tid < HD) qv[tid] = q[base_bh + qi*Dd + tid];
    __syncthreads();

    float s;
    if (tid <= qi) {
        const float* kp = &k[base_bh + tid*Dd];
        s = 0.f;
        #pragma unroll
        for (int d2 = 0; d2 < HD; d2++) s += qv[d2] * kp[d2];
        s *= 0.125f;
    } else {
        s = -1e30f;
    }
    red[tid] = s; __syncthreads();
    for (int st = 128; st > 0; st >>= 1) {
        if (tid < st) red[tid] = fmaxf(red[tid], red[tid+st]);
        __syncthreads();
    }
    float mx = red[0];
    __syncthreads();
    float e = expf(s - mx);
    p[tid] = e;
    red[tid] = e; __syncthreads();
    for (int st = 128; st > 0; st >>= 1) {
        if (tid < st) red[tid] += red[tid+st];
        __syncthreads();
    }
    float inv = 1.f / red[0];
    __syncthreads();

    // parallel V accumulation: 4 groups x 64 channels
    int d = tid & 63, grp = tid >> 6;
    float acc = 0.f;
    for (int t2 = grp; t2 <= qi; t2 += 4)
        acc += p[t2] * v[base_bh + t2*Dd + d];
    red[tid] = acc;
    __syncthreads();
    if (tid < HD)
        o[base_bh + qi*Dd + tid] =
            (red[tid] + red[tid+64] + red[tid+128] + red[tid+192]) * inv;
}

// ---------------- parallel pooling: pooled[b][d] = mean_s x[b,s,d] ----------------
__global__ void pool_k(const float* __restrict__ x, float* __restrict__ pooled) {
    int b = blockIdx.y;
    int d = blockIdx.x*128 + threadIdx.x;
    float s = 0.f;
    #pragma unroll 4
    for (int ss = 0; ss < Ss; ss++) s += x[(size_t)(b*Ss+ss)*Dd + d];
    pooled[b*Dd + d] = s * (1.f/Ss);
}

// ---------------- gating + routing (single block, reads pooled) ----------------
__global__ void gate_k(const float* __restrict__ pooled, const float* __restrict__ gw) {
    __shared__ float red[512];
    __shared__ float sc[2*(Cc+1)];
    int tid = threadIdx.x;            // 512
    for (int idx = 0; idx < 2*(Cc+1); idx++) {
        int b = idx / (Cc+1), c = idx % (Cc+1);
        red[tid] = pooled[b*Dd + tid] * gw[tid*(Cc+1) + c];
        __syncthreads();
        for (int s = 256; s > 0; s >>= 1) {
            if (tid < s) red[tid] += red[tid+s];
            __syncthreads();
        }
        if (tid == 0) sc[idx] = red[0];
        __syncthreads();
    }
    if (tid == 0) {
        float p[Bb][Cc+1];
        for (int b = 0; b < Bb; b++) {
            float mx = -1e30f;
            for (int c = 0; c < Cc+1; c++) mx = fmaxf(mx, sc[b*(Cc+1)+c]);
            float sum = 0.f;
            for (int c = 0; c < Cc+1; c++) { p[b][c] = expf(sc[b*(Cc+1)+c] - mx); sum += p[b][c]; }
            for (int c = 0; c < Cc+1; c++) p[b][c] /= sum;
        }
        float lb = 0.f;
        for (int c = 0; c < Cc+1; c++) {
            g_accp[c] += p[0][c] + p[1][c];
            float avg = 0.5f * (p[0][c] + p[1][c]);
            lb += avg*avg;
        }
        g_acclb += (float)(Cc+1) * lb;
        for (int b = 0; b < Bb; b++) {
            int co = g_cur[b];
            int j1 = (co+1) & 3, j2 = (co+2) & 3;
            float s1 = sc[b*(Cc+1)+j1], s2 = sc[b*(Cc+1)+j2];
            int w;
            if (s1 > s2) w = j1;
            else if (s2 > s1) w = j2;
            else w = (j1 < j2) ? j1 : j2;
            g_cur[b] = w;
        }
    }
}

// ---------------- finalize aux losses ----------------
__global__ void fin_k(float* __restrict__ out, int n) {
    if (threadIdx.x == 0) {
        float avg[Cc+1];
        float m = 0.f;
        for (int i = 0; i < Cc+1; i++) { avg[i] = g_accp[i] * 0.25f; m += avg[i]; }
        m *= 1.f/(Cc+1);
        float var = 0.f;
        for (int i = 0; i < Cc+1; i++) { float d = avg[i] - m; var += d*d; }
        var *= 1.f/(Cc+1);
        out[n-2] = var;
        out[n-1] = g_acclb * 0.5f;
    }
}

// ---------------- host orchestration ----------------
extern "C" void kernel_launch(void* const* d_in, const int* in_sizes, int n_in,
                              void* d_out, int out_size) {
    const int*   ids   = (const int*)  d_in[0];
    const int*   start = (const int*)  d_in[1];
    const float* emb   = (const float*)d_in[2];
    const float* Wq    = (const float*)d_in[3];
    const float* Wk    = (const float*)d_in[4];
    const float* Wv    = (const float*)d_in[5];
    const float* Wo    = (const float*)d_in[6];
    const float* W1    = (const float*)d_in[7];
    const float* W2    = (const float*)d_in[8];
    const float* n1    = (const float*)d_in[9];
    const float* n2    = (const float*)d_in[10];
    const float* gw    = (const float*)d_in[11];
    const float* fnw   = (const float*)d_in[12];
    const float* fcw   = (const float*)d_in[13];
    float* out = (float*)d_out;

    float *x, *xn, *q, *k, *v, *o, *ff, *pool;
    int* cur;
    cudaGetSymbolAddress((void**)&x,  g_x);
    cudaGetSymbolAddress((void**)&xn, g_xn);
    cudaGetSymbolAddress((void**)&q,  g_q);
    cudaGetSymbolAddress((void**)&k,  g_k);
    cudaGetSymbolAddress((void**)&v,  g_v);
    cudaGetSymbolAddress((void**)&o,  g_o);
    cudaGetSymbolAddress((void**)&ff, g_ff);
    cudaGetSymbolAddress((void**)&pool, g_pool);
    cudaGetSymbolAddress((void**)&cur, g_cur);

    static int smem_set = 0;
    if (!smem_set) {
        cudaFuncSetAttribute(gemm_tc, cudaFuncAttributeMaxDynamicSharedMemorySize, TC_SMEM);
        smem_set = 1;
    }

    init_k<<<1, 32>>>(start);
    embed_k<<<TOK, Dd>>>(ids, emb, x);

    dim3 gqkv(Dd/64, TOK/64, 3);
    dim3 gwo (Dd/64, TOK/64);
    dim3 gw1 (Ff/64, TOK/64);
    dim3 gw2 (Dd/64, TOK/64);
    for (int step = 0; step < 2; step++) {
        rmsnorm_k<<<TOK, Dd>>>(x, n1, cur, xn);
        qkv_tc<<<gqkv, 256>>>(xn, Wq, Wk, Wv, q, k, v, cur);
        rope_k<<<TOK, 256>>>(q, k);
        attn_k<<<dim3(Ss, Hh, Bb), 256>>>(q, k, v, o);
        gemm_mid_tc<<<gwo, 256>>>(o, Wo, x, x, cur, Dd, Dd, 1);
        rmsnorm_k<<<TOK, Dd>>>(x, n2, cur, xn);
        gemm_mid_tc<<<gw1, 256>>>(xn, W1, nullptr, ff, cur, Dd, Ff, 2);
        gemm_mid_tc<<<gw2, 256>>>(ff, W2, x, x, cur, Ff, Dd, 1);
        pool_k<<<dim3(Dd/128, Bb), 128>>>(x, pool);
        gate_k<<<1, 512>>>(pool, gw);
    }
    rmsnorm_k<<<TOK, Dd>>>(x, fnw, nullptr, xn);
    gemm_tc<<<dim3(TOK/128, Vv/128), 256, TC_SMEM>>>(xn, fcw, out, Dd, Vv);
    fin_k<<<1, 32>>>(out, out_size);
}

// round 7
// speedup vs baseline: 2.0633x; 1.1290x over previous
#include <cuda_runtime.h>
#include <math.h>
#include <stdint.h>

#define Dd  512
#define Hh  8
#define HD  64
#define Bb  2
#define Ss  256
#define Ff  2048
#define Cc  4
#define Vv  32000
#define TOK (Bb*Ss)   // 512

// ---------------- device state (no allocation allowed) ----------------
__device__ float g_x [TOK*Dd];
__device__ float g_xn[TOK*Dd];
__device__ float g_q [TOK*Dd];
__device__ float g_k [TOK*Dd];
__device__ float g_v [TOK*Dd];
__device__ float g_o [TOK*Dd];
__device__ float g_ff[TOK*Ff];
__device__ float g_part[6*TOK*Dd];
__device__ float g_pool[Bb*Dd];
__device__ int   g_cur[Bb];
__device__ float g_accp[Cc+1];
__device__ float g_acclb;

// ---------------- init ----------------
__global__ void init_k(const int* __restrict__ start) {
    if (threadIdx.x == 0) {
        g_cur[0] = start[0];
        g_cur[1] = start[1];
        #pragma unroll
        for (int i = 0; i < Cc+1; i++) g_accp[i] = 0.f;
        g_acclb = 0.f;
    }
}

// ---------------- embedding ----------------
__global__ void embed_k(const int* __restrict__ ids, const float* __restrict__ emb,
                        float* __restrict__ x) {
    int t = blockIdx.x;
    int d = threadIdx.x;
    float scale = sqrtf((float)Dd);
    x[t*Dd + d] = emb[(size_t)ids[t]*Dd + d] * scale;
}

// ---------------- rmsnorm (block per token) ----------------
__global__ void rmsnorm_k(const float* __restrict__ x, const float* __restrict__ w,
                          const int* __restrict__ cur, float* __restrict__ out) {
    int t = blockIdx.x;
    int d = threadIdx.x;          // 512
    __shared__ float red[512];
    float v = x[t*Dd + d];
    red[d] = v*v;
    __syncthreads();
    for (int s = 256; s > 0; s >>= 1) {
        if (d < s) red[d] += red[d+s];
        __syncthreads();
    }
    float scale = rsqrtf(red[0] * (1.0f/Dd) + 1e-6f);
    const float* ww = w;
    if (cur) ww += (size_t)cur[t / Ss] * Dd;
    out[t*Dd + d] = v * scale * ww[d];
}

// ---------------- tf32 / cp.async helpers ----------------
__device__ __forceinline__ uint32_t f2tf32(float f) {
    uint32_t u;
    asm volatile("cvt.rna.tf32.f32 %0, %1;" : "=r"(u) : "f"(f));
    return u;
}

__device__ __forceinline__ void mma_tf32(float c[4],
    uint32_t a0, uint32_t a1, uint32_t a2, uint32_t a3,
    uint32_t b0, uint32_t b1)
{
    asm volatile(
        "mma.sync.aligned.m16n8k8.row.col.f32.tf32.tf32.f32 "
        "{%0,%1,%2,%3}, {%4,%5,%6,%7}, {%8,%9}, {%0,%1,%2,%3};"
        : "+f"(c[0]), "+f"(c[1]), "+f"(c[2]), "+f"(c[3])
        : "r"(a0), "r"(a1), "r"(a2), "r"(a3), "r"(b0), "r"(b1));
}

__device__ __forceinline__ void cp_async16(float* smem, const float* gmem) {
    uint32_t s;
    asm("{ .reg .u64 t; cvta.to.shared.u64 t, %1; cvt.u32.u64 %0, t; }"
        : "=r"(s) : "l"(smem));
    asm volatile("cp.async.cg.shared.global [%0], [%1], 16;" :: "r"(s), "l"(gmem) : "memory");
}
#define CP_COMMIT()  asm volatile("cp.async.commit_group;" ::: "memory")
#define CP_WAIT1()   asm volatile("cp.async.wait_group 1;" ::: "memory")
#define CP_WAIT0()   asm volatile("cp.async.wait_group 0;" ::: "memory")

// ---------------- tensor-core logits GEMM (tf32, cp.async double-buffered) ------
#define TC_SMEM ((2*128*36 + 2*32*136) * (int)sizeof(float))
__global__ void __launch_bounds__(256,2) gemm_tc(
    const float* __restrict__ A, const float* __restrict__ W,
    float* __restrict__ Out, int K, int N)
{
    extern __shared__ float dsm[];
    float (*As)[128][36]  = (float(*)[128][36])dsm;
    float (*Bs)[32][136]  = (float(*)[32][136])(dsm + 2*128*36);
    int tid = threadIdx.x;
    int m0 = blockIdx.x*128, n0 = blockIdx.y*128;
    int warp = tid >> 5, lane = tid & 31;
    int wm = warp & 1, wn = warp >> 1;
    int g = lane >> 2, tg = lane & 3;

    auto issue = [&](int k0, int buf) {
        #pragma unroll
        for (int l = 0; l < 4; l++) {
            int idx = tid + l*256;
            int row = idx >> 3, kc = (idx & 7) * 4;
            cp_async16(&As[buf][row][kc], &A[(size_t)(m0+row)*K + k0 + kc]);
        }
        #pragma unroll
        for (int l = 0; l < 4; l++) {
            int idx = tid + l*256;
            int kr = idx >> 5, nc = (idx & 31) * 4;
            cp_async16(&Bs[buf][kr][nc], &W[(size_t)(k0+kr)*N + n0 + nc]);
        }
        CP_COMMIT();
    };

    float acc[4][4][4] = {};
    int nk = K / 32;
    issue(0, 0);
    int buf = 0;
    for (int it = 0; it < nk; it++) {
        bool more = (it + 1) < nk;
        if (more) issue((it+1)*32, buf^1);
        if (more) CP_WAIT1(); else CP_WAIT0();
        __syncthreads();

        #pragma unroll
        for (int kk = 0; kk < 32; kk += 8) {
            uint32_t af[4][4], bf[4][2];
            #pragma unroll
            for (int mt = 0; mt < 4; mt++) {
                int mrow = wm*64 + mt*16 + g;
                af[mt][0] = f2tf32(As[buf][mrow  ][kk+tg]);
                af[mt][1] = f2tf32(As[buf][mrow+8][kk+tg]);
                af[mt][2] = f2tf32(As[buf][mrow  ][kk+tg+4]);
                af[mt][3] = f2tf32(As[buf][mrow+8][kk+tg+4]);
            }
            #pragma unroll
            for (int nt = 0; nt < 4; nt++) {
                int ncol = wn*32 + nt*8 + g;
                bf[nt][0] = f2tf32(Bs[buf][kk+tg  ][ncol]);
                bf[nt][1] = f2tf32(Bs[buf][kk+tg+4][ncol]);
            }
            #pragma unroll
            for (int mt = 0; mt < 4; mt++)
                #pragma unroll
                for (int nt = 0; nt < 4; nt++)
                    mma_tf32(acc[mt][nt], af[mt][0], af[mt][1], af[mt][2], af[mt][3],
                             bf[nt][0], bf[nt][1]);
        }
        __syncthreads();
        buf ^= 1;
    }

    #pragma unroll
    for (int mt = 0; mt < 4; mt++) {
        #pragma unroll
        for (int nt = 0; nt < 4; nt++) {
            int row = m0 + wm*64 + mt*16 + g;
            int col = n0 + wn*32 + nt*8 + 2*tg;
            float2 lo = { acc[mt][nt][0], acc[mt][nt][1] };
            float2 hi = { acc[mt][nt][2], acc[mt][nt][3] };
            *(float2*)&Out[(size_t)row*N + col]     = lo;
            *(float2*)&Out[(size_t)(row+8)*N + col] = hi;
        }
    }
}

// ---------------- tf32x3 mid GEMM core (cp.async double-buffered) ----------------
// 64x64 block tile, BK=32. A has row stride lda; K is the k-extent to process.
__device__ __forceinline__ void tc64_core(
    const float* __restrict__ A, int lda, const float* __restrict__ W,
    int K, int N, int m0, int n0, int tid, float acc[2][2][4])
{
    __shared__ float As[2][64][36];
    __shared__ float Bs[2][32][72];
    int warp = tid >> 5, lane = tid & 31;
    int wm = warp & 1, wn = warp >> 1;
    int g = lane >> 2, tg = lane & 3;

    auto issue = [&](int k0, int buf) {
        #pragma unroll
        for (int l = 0; l < 2; l++) {
            int idx = tid + l*256;
            int row = idx >> 3, kc = (idx & 7) * 4;
            cp_async16(&As[buf][row][kc], &A[(size_t)(m0+row)*lda + k0 + kc]);
        }
        #pragma unroll
        for (int l = 0; l < 2; l++) {
            int idx = tid + l*256;
            int kr = idx >> 4, nc = (idx & 15) * 4;
            cp_async16(&Bs[buf][kr][nc], &W[(size_t)(k0+kr)*N + n0 + nc]);
        }
        CP_COMMIT();
    };

    int nk = K / 32;
    issue(0, 0);
    int buf = 0;
    for (int it = 0; it < nk; it++) {
        bool more = (it + 1) < nk;
        if (more) issue((it+1)*32, buf^1);
        if (more) CP_WAIT1(); else CP_WAIT0();
        __syncthreads();

        #pragma unroll
        for (int kk = 0; kk < 32; kk += 8) {
            uint32_t ah[2][4], al[2][4], bh[2][2], bl[2][2];
            #pragma unroll
            for (int mt = 0; mt < 2; mt++) {
                int mrow = wm*32 + mt*16 + g;
                float a0 = As[buf][mrow  ][kk+tg];
                float a1 = As[buf][mrow+8][kk+tg];
                float a2 = As[buf][mrow  ][kk+tg+4];
                float a3 = As[buf][mrow+8][kk+tg+4];
                ah[mt][0] = f2tf32(a0); al[mt][0] = f2tf32(a0 - __uint_as_float(ah[mt][0]));
                ah[mt][1] = f2tf32(a1); al[mt][1] = f2tf32(a1 - __uint_as_float(ah[mt][1]));
                ah[mt][2] = f2tf32(a2); al[mt][2] = f2tf32(a2 - __uint_as_float(ah[mt][2]));
                ah[mt][3] = f2tf32(a3); al[mt][3] = f2tf32(a3 - __uint_as_float(ah[mt][3]));
            }
            #pragma unroll
            for (int nt = 0; nt < 2; nt++) {
                int ncol = wn*16 + nt*8 + g;
                float b0 = Bs[buf][kk+tg  ][ncol];
                float b1 = Bs[buf][kk+tg+4][ncol];
                bh[nt][0] = f2tf32(b0); bl[nt][0] = f2tf32(b0 - __uint_as_float(bh[nt][0]));
                bh[nt][1] = f2tf32(b1); bl[nt][1] = f2tf32(b1 - __uint_as_float(bh[nt][1]));
            }
            #pragma unroll
            for (int mt = 0; mt < 2; mt++)
                #pragma unroll
                for (int nt = 0; nt < 2; nt++) {
                    mma_tf32(acc[mt][nt], ah[mt][0], ah[mt][1], ah[mt][2], ah[mt][3],
                             bl[nt][0], bl[nt][1]);
                    mma_tf32(acc[mt][nt], al[mt][0], al[mt][1], al[mt][2], al[mt][3],
                             bh[nt][0], bh[nt][1]);
                    mma_tf32(acc[mt][nt], ah[mt][0], ah[mt][1], ah[mt][2], ah[mt][3],
                             bh[nt][0], bh[nt][1]);
                }
        }
        __syncthreads();
        buf ^= 1;
    }
}

// shared epilogue for 64x64 tc tiles
__device__ __forceinline__ void tc64_epilogue(
    float acc[2][2][4], const float* __restrict__ res, float* __restrict__ Out,
    int N, int m0, int n0, int tid, int epi)
{
    int warp = tid >> 5, lane = tid & 31;
    int wm = warp & 1, wn = warp >> 1;
    int g = lane >> 2, tg = lane & 3;
    #pragma unroll
    for (int mt = 0; mt < 2; mt++) {
        #pragma unroll
        for (int nt = 0; nt < 2; nt++) {
            int row = m0 + wm*32 + mt*16 + g;
            int col = n0 + wn*16 + nt*8 + 2*tg;
            float2 lo = { acc[mt][nt][0], acc[mt][nt][1] };
            float2 hi = { acc[mt][nt][2], acc[mt][nt][3] };
            if (epi == 1) {
                float2 r0 = *(const float2*)&res[(size_t)row*N + col];
                float2 r1 = *(const float2*)&res[(size_t)(row+8)*N + col];
                lo.x += r0.x; lo.y += r0.y;
                hi.x += r1.x; hi.y += r1.y;
            } else if (epi == 2) {
                lo.x = lo.x / (1.f + expf(-lo.x));
                lo.y = lo.y / (1.f + expf(-lo.y));
                hi.x = hi.x / (1.f + expf(-hi.x));
                hi.y = hi.y / (1.f + expf(-hi.y));
            }
            *(float2*)&Out[(size_t)row*N + col]     = lo;
            *(float2*)&Out[(size_t)(row+8)*N + col] = hi;
        }
    }
}

// ---------------- mid GEMM, direct (used for W1) ----------------
__global__ void __launch_bounds__(256) gemm_mid_tc(
    const float* __restrict__ A, const float* __restrict__ Wb,
    const float* __restrict__ res, float* __restrict__ Out,
    const int* __restrict__ cur, int K, int N, int epi)
{
    int m0 = blockIdx.y*64, n0 = blockIdx.x*64;
    const float* W = Wb;
    if (cur) W += (size_t)cur[m0 / Ss] * K * N;
    float acc[2][2][4] = {};
    tc64_core(A, K, W, K, N, m0, n0, threadIdx.x, acc);
    tc64_epilogue(acc, res, Out, N, m0, n0, threadIdx.x, epi);
}

// ---------------- split-K mid GEMM -> partials (N = Dd) ----------------
// grid.z = split index; partial z stored at part + z*TOK*Dd
__global__ void __launch_bounds__(256) gemm_sk(
    const float* __restrict__ A, const float* __restrict__ Wb,
    float* __restrict__ part, const int* __restrict__ cur, int Kfull, int klen)
{
    int m0 = blockIdx.y*64, n0 = blockIdx.x*64;
    int z = blockIdx.z;
    const float* W = Wb + (size_t)cur[m0 / Ss] * Kfull * Dd + (size_t)z * klen * Dd;
    float acc[2][2][4] = {};
    tc64_core(A + (size_t)z * klen, Kfull, W, klen, Dd, m0, n0, threadIdx.x, acc);
    tc64_epilogue(acc, nullptr, part + (size_t)z * TOK * Dd, Dd, m0, n0, threadIdx.x, 0);
}

// ---------------- split-K QKV -> partials ----------------
// grid.z in [0,6): op = z>>1 (0=q,1=k,2=v), half = z&1 (k-range)
__global__ void __launch_bounds__(256) qkv_sk(
    const float* __restrict__ xn,
    const float* __restrict__ Wq, const float* __restrict__ Wk, const float* __restrict__ Wv,
    float* __restrict__ part, const int* __restrict__ cur)
{
    int z = blockIdx.z;
    int op = z >> 1, half = z & 1;
    const float* Wb = (op == 0) ? Wq : (op == 1) ? Wk : Wv;
    int m0 = blockIdx.y*64, n0 = blockIdx.x*64;
    const float* W = Wb + (size_t)cur[m0 / Ss] * Dd * Dd + (size_t)half * 256 * Dd;
    float acc[2][2][4] = {};
    tc64_core(xn + (size_t)half * 256, Dd, W, 256, Dd, m0, n0, threadIdx.x, acc);
    tc64_epilogue(acc, nullptr, part + (size_t)z * TOK * Dd, Dd, m0, n0, threadIdx.x, 0);
}

// ---------------- reduce: q,k,v from 6 partials ----------------
__global__ void qkv_red(const float* __restrict__ part,
                        float* __restrict__ q, float* __restrict__ k, float* __restrict__ v) {
    int i = blockIdx.x*256 + threadIdx.x;
    q[i] = part[i]             + part[i + TOK*Dd];
    k[i] = part[i + 2*TOK*Dd]  + part[i + 3*TOK*Dd];
    v[i] = part[i + 4*TOK*Dd]  + part[i + 5*TOK*Dd];
}

// ---------------- reduce: x += sum of S partials ----------------
__global__ void red_add(float* __restrict__ x, const float* __restrict__ part, int S) {
    int i = blockIdx.x*256 + threadIdx.x;
    float s = x[i];
    for (int j = 0; j < S; j++) s += part[(size_t)j*TOK*Dd + i];
    x[i] = s;
}

// ---------------- rope on q,k ----------------
__global__ void rope_k(float* __restrict__ q, float* __restrict__ k) {
    int t = blockIdx.x;
    int s = t % Ss;
    int i = threadIdx.x;
    int h = i >> 5;
    int j = i & 31;
    float inv = powf(10000.f, -(2.f*j) / 64.f);
    float ang = (float)s * inv;
    float c = cosf(ang), sn = sinf(ang);
    int base = t*Dd + h*HD + 2*j;
    float q1 = q[base], q2 = q[base+1];
    q[base]   = q1*c - q2*sn;
    q[base+1] = q1*sn + q2*c;
    float k1 = k[base], k2 = k[base+1];
    k[base]   = k1*c - k2*sn;
    k[base+1] = k1*sn + k2*c;
}

// ---------------- causal attention: block per (b,h,q-row) ----------------
__global__ void attn_k(const float* __restrict__ q, const float* __restrict__ k,
                       const float* __restrict__ v, float* __restrict__ o) {
    int qi = blockIdx.x, h = blockIdx.y, b = blockIdx.z;
    int tid = threadIdx.x;            // 256
    __shared__ float qv[HD];
    __shared__ float p[Ss];
    __shared__ float red[Ss];
    int base_bh = b*Ss*Dd + h*HD;
    if (tid < HD) qv[tid] = q[base_bh + qi*Dd + tid];
    __syncthreads();

    float s;
    if (tid <= qi) {
        const float* kp = &k[base_bh + tid*Dd];
        s = 0.f;
        #pragma unroll
        for (int d2 = 0; d2 < HD; d2++) s += qv[d2] * kp[d2];
        s *= 0.125f;
    } else {
        s = -1e30f;
    }
    red[tid] = s; __syncthreads();
    for (int st = 128; st > 0; st >>= 1) {
        if (tid < st) red[tid] = fmaxf(red[tid], red[tid+st]);
        __syncthreads();
    }
    float mx = red[0];
    __syncthreads();
    float e = expf(s - mx);
    p[tid] = e;
    red[tid] = e; __syncthreads();
    for (int st = 128; st > 0; st >>= 1) {
        if (tid < st) red[tid] += red[tid+st];
        __syncthreads();
    }
    float inv = 1.f / red[0];
    __syncthreads();

    int d = tid & 63, grp = tid >> 6;
    float acc = 0.f;
    for (int t2 = grp; t2 <= qi; t2 += 4)
        acc += p[t2] * v[base_bh + t2*Dd + d];
    red[tid] = acc;
    __syncthreads();
    if (tid < HD)
        o[base_bh + qi*Dd + tid] =
            (red[tid] + red[tid+64] + red[tid+128] + red[tid+192]) * inv;
}

// ---------------- parallel pooling ----------------
__global__ void pool_k(const float* __restrict__ x, float* __restrict__ pooled) {
    int b = blockIdx.y;
    int d = blockIdx.x*128 + threadIdx.x;
    float s = 0.f;
    #pragma unroll 4
    for (int ss = 0; ss < Ss; ss++) s += x[(size_t)(b*Ss+ss)*Dd + d];
    pooled[b*Dd + d] = s * (1.f/Ss);
}

// ---------------- gating + routing (single block, reads pooled) ----------------
__global__ void gate_k(const float* __restrict__ pooled, const float* __restrict__ gw) {
    __shared__ float red[512];
    __shared__ float sc[2*(Cc+1)];
    int tid = threadIdx.x;            // 512
    for (int idx = 0; idx < 2*(Cc+1); idx++) {
        int b = idx / (Cc+1), c = idx % (Cc+1);
        red[tid] = pooled[b*Dd + tid] * gw[tid*(Cc+1) + c];
        __syncthreads();
        for (int s = 256; s > 0; s >>= 1) {
            if (tid < s) red[tid] += red[tid+s];
            __syncthreads();
        }
        if (tid == 0) sc[idx] = red[0];
        __syncthreads();
    }
    if (tid == 0) {
        float p[Bb][Cc+1];
        for (int b = 0; b < Bb; b++) {
            float mx = -1e30f;
            for (int c = 0; c < Cc+1; c++) mx = fmaxf(mx, sc[b*(Cc+1)+c]);
            float sum = 0.f;
            for (int c = 0; c < Cc+1; c++) { p[b][c] = expf(sc[b*(Cc+1)+c] - mx); sum += p[b][c]; }
            for (int c = 0; c < Cc+1; c++) p[b][c] /= sum;
        }
        float lb = 0.f;
        for (int c = 0; c < Cc+1; c++) {
            g_accp[c] += p[0][c] + p[1][c];
            float avg = 0.5f * (p[0][c] + p[1][c]);
            lb += avg*avg;
        }
        g_acclb += (float)(Cc+1) * lb;
        for (int b = 0; b < Bb; b++) {
            int co = g_cur[b];
            int j1 = (co+1) & 3, j2 = (co+2) & 3;
            float s1 = sc[b*(Cc+1)+j1], s2 = sc[b*(Cc+1)+j2];
            int w;
            if (s1 > s2) w = j1;
            else if (s2 > s1) w = j2;
            else w = (j1 < j2) ? j1 : j2;
            g_cur[b] = w;
        }
    }
}

// ---------------- finalize aux losses ----------------
__global__ void fin_k(float* __restrict__ out, int n) {
    if (threadIdx.x == 0) {
        float avg[Cc+1];
        float m = 0.f;
        for (int i = 0; i < Cc+1; i++) { avg[i] = g_accp[i] * 0.25f; m += avg[i]; }
        m *= 1.f/(Cc+1);
        float var = 0.f;
        for (int i = 0; i < Cc+1; i++) { float d = avg[i] - m; var += d*d; }
        var *= 1.f/(Cc+1);
        out[n-2] = var;
        out[n-1] = g_acclb * 0.5f;
    }
}

// ---------------- host orchestration ----------------
extern "C" void kernel_launch(void* const* d_in, const int* in_sizes, int n_in,
                              void* d_out, int out_size) {
    const int*   ids   = (const int*)  d_in[0];
    const int*   start = (const int*)  d_in[1];
    const float* emb   = (const float*)d_in[2];
    const float* Wq    = (const float*)d_in[3];
    const float* Wk    = (const float*)d_in[4];
    const float* Wv    = (const float*)d_in[5];
    const float* Wo    = (const float*)d_in[6];
    const float* W1    = (const float*)d_in[7];
    const float* W2    = (const float*)d_in[8];
    const float* n1    = (const float*)d_in[9];
    const float* n2    = (const float*)d_in[10];
    const float* gw    = (const float*)d_in[11];
    const float* fnw   = (const float*)d_in[12];
    const float* fcw   = (const float*)d_in[13];
    float* out = (float*)d_out;

    float *x, *xn, *q, *k, *v, *o, *ff, *part, *pool;
    int* cur;
    cudaGetSymbolAddress((void**)&x,  g_x);
    cudaGetSymbolAddress((void**)&xn, g_xn);
    cudaGetSymbolAddress((void**)&q,  g_q);
    cudaGetSymbolAddress((void**)&k,  g_k);
    cudaGetSymbolAddress((void**)&v,  g_v);
    cudaGetSymbolAddress((void**)&o,  g_o);
    cudaGetSymbolAddress((void**)&ff, g_ff);
    cudaGetSymbolAddress((void**)&part, g_part);
    cudaGetSymbolAddress((void**)&pool, g_pool);
    cudaGetSymbolAddress((void**)&cur, g_cur);

    static int smem_set = 0;
    if (!smem_set) {
        cudaFuncSetAttribute(gemm_tc, cudaFuncAttributeMaxDynamicSharedMemorySize, TC_SMEM);
        smem_set = 1;
    }

    init_k<<<1, 32>>>(start);
    embed_k<<<TOK, Dd>>>(ids, emb, x);

    int nred = TOK*Dd/256;            // 1024 blocks
    dim3 gqkv(Dd/64, TOK/64, 6);      // 384 blocks (split-K=2 x q,k,v)
    dim3 gwo (Dd/64, TOK/64, 2);      // 128 blocks (split-K=2)
    dim3 gw1 (Ff/64, TOK/64);         // 256 blocks
    dim3 gw2 (Dd/64, TOK/64, 4);      // 256 blocks (split-K=4)
    for (int step = 0; step < 2; step++) {
        rmsnorm_k<<<TOK, Dd>>>(x, n1, cur, xn);
        qkv_sk<<<gqkv, 256>>>(xn, Wq, Wk, Wv, part, cur);
        qkv_red<<<nred, 256>>>(part, q, k, v);
        rope_k<<<TOK, 256>>>(q, k);
        attn_k<<<dim3(Ss, Hh, Bb), 256>>>(q, k, v, o);
        gemm_sk<<<gwo, 256>>>(o, Wo, part, cur, Dd, 256);
        red_add<<<nred, 256>>>(x, part, 2);
        rmsnorm_k<<<TOK, Dd>>>(x, n2, cur, xn);
        gemm_mid_tc<<<gw1, 256>>>(xn, W1, nullptr, ff, cur, Dd, Ff, 2);
        gemm_sk<<<gw2, 256>>>(ff, W2, part, cur, Ff, 512);
        red_add<<<nred, 256>>>(x, part, 4);
        pool_k<<<dim3(Dd/128, Bb), 128>>>(x, pool);
        gate_k<<<1, 512>>>(pool, gw);
    }
    rmsnorm_k<<<TOK, Dd>>>(x, fnw, nullptr, xn);
    gemm_tc<<<dim3(TOK/128, Vv/128), 256, TC_SMEM>>>(xn, fcw, out, Dd, Vv);
    fin_k<<<1, 32>>>(out, out_size);
}